// round 8
// baseline (speedup 1.0000x reference)
#include <cuda_runtime.h>
#include <cstdint>

#define DI __device__ __forceinline__

namespace {
constexpr int B = 4, S = 512, H = 512, NH = 8, T = 3, DH = 64, DTS = 170;
constexpr int MTOK = B * S;
constexpr int H3 = 3 * H;
constexpr int H4 = 4 * H;
constexpr int BSS = B * S * S;
constexpr float EPS = 1e-5f;
constexpr int NLUT = 16384;
constexpr float MMAX = 5.6400f;
}

// ---------------- scratch ------------------------------------------------------
__device__ float g_qkv3[3 * MTOK * H3];
__device__ float g_attn_o3[3 * MTOK * H];
__device__ float g_combined[MTOK * H3];
__device__ float g_combined_tf[MTOK * H3];
__device__ float g_mask3[T * BSS];
__device__ float g_m[MTOK * H];
__device__ float g_big[MTOK * H4];
__device__ float g_weighted[MTOK * H];
__device__ float g_weighted_tf[MTOK * H];
__device__ float g_h1[MTOK * H];
__device__ float g_h1tf[MTOK * H];
__device__ float g_h2[MTOK * H];
__device__ float g_xtf[MTOK * H];
__device__ float g_lut[T * 3 * (NLUT + 1)];
// tf32 weight copies
__device__ float g_w_qkv[3 * H * H3];
__device__ float g_w_ao[3 * H * H];
__device__ float g_w_m1[H3 * H];
__device__ float g_w_eq[H * H3];
__device__ float g_w_eo[H * H];
__device__ float g_w_f1[H * H4];
__device__ float g_w_f2[H4 * H];
__device__ float g_w_op[H * H];

DI float geluf(float x) { return 0.5f * x * (1.0f + erff(x * 0.7071067811865475f)); }

DI uint32_t tf32cvt(float x) {
    uint32_t r;
    asm("cvt.rna.tf32.f32 %0, %1;" : "=r"(r) : "f"(x));
    return r;
}
DI float tf32r(float x) { return __uint_as_float(tf32cvt(x)); }

DI void mma_tf32(float* c, uint32_t a0, uint32_t a1, uint32_t a2, uint32_t a3,
                 uint32_t b0, uint32_t b1) {
    asm volatile(
        "mma.sync.aligned.m16n8k8.row.col.f32.tf32.tf32.f32 "
        "{%0,%1,%2,%3}, {%4,%5,%6,%7}, {%8,%9}, {%0,%1,%2,%3};"
        : "+f"(c[0]), "+f"(c[1]), "+f"(c[2]), "+f"(c[3])
        : "r"(a0), "r"(a1), "r"(a2), "r"(a3), "r"(b0), "r"(b1));
}

DI void ldsm4(uint32_t* r, uint32_t addr) {
    asm volatile("ldmatrix.sync.aligned.m8n8.x4.shared.b16 {%0,%1,%2,%3}, [%4];"
                 : "=r"(r[0]), "=r"(r[1]), "=r"(r[2]), "=r"(r[3]) : "r"(addr));
}

DI uint32_t smem_u32(const void* p) { return (uint32_t)__cvta_generic_to_shared(p); }
DI void cp16(uint32_t dst, const void* src) {
    asm volatile("cp.async.cg.shared.global [%0], [%1], 16;" :: "r"(dst), "l"(src));
}
DI void cp_commit() { asm volatile("cp.async.commit_group;"); }
template <int N> DI void cp_wait() { asm volatile("cp.async.wait_group %0;" :: "n"(N)); }

// ---------------- consolidated tf32 rounding (9 segments, one launch) ----------
struct RtArgs {
    const float4* src[9];
    float4* dst[9];
};
__global__ void roundtf_all(RtArgs a) {
    constexpr int bnd[10] = {
        0,
        262144,    // x          : 1048576 f
        851968,    // qkv_W      : +589824
        1048576,   // attn_out_W : +196608
        1245184,   // mixer_W1   : +196608
        1441792,   // el_qkv_W   : +196608
        1507328,   // el_out_W   : +65536
        1769472,   // el_ff_W1   : +262144
        2031616,   // el_ff_W2   : +262144
        2097152    // op_W       : +65536
    };
    int i = blockIdx.x * blockDim.x + threadIdx.x;
    if (i >= bnd[9]) return;
#pragma unroll
    for (int s = 0; s < 9; s++) {
        if (i >= bnd[s] && i < bnd[s + 1]) {
            int j = i - bnd[s];
            float4 v = a.src[s][j];
            float4 o;
            o.x = tf32r(v.x); o.y = tf32r(v.y); o.z = tf32r(v.z); o.w = tf32r(v.w);
            a.dst[s][j] = o;
            return;
        }
    }
}

// ---------------- LUT builder --------------------------------------------------
__global__ void build_lut_kernel(const float* __restrict__ encW,
                                 const float* __restrict__ encB,
                                 const float* __restrict__ lng,
                                 const float* __restrict__ lnb) {
    int idx = blockIdx.x * blockDim.x + threadIdx.x;
    const int total = T * 3 * (NLUT + 1);
    if (idx >= total) return;
    int j = idx % (NLUT + 1);
    int d = (idx / (NLUT + 1)) % 3;
    int t = idx / (3 * (NLUT + 1));
    float df = (float)(d - 1);
    float scale = (t == 0) ? 1.0f : ((t == 1) ? 0.1f : 0.01f);
    float m = (MMAX / NLUT) * (float)j * scale;
    const float* W0 = encW + t * 2 * DTS;
    const float* W1 = W0 + DTS;
    const float* eb = encB + t * DTS;
    const float* gg = lng + t * DTS;
    const float* bb = lnb + t * DTS;
    float s1 = 0.f, s2 = 0.f;
    for (int jj = 0; jj < DTS; jj++) {
        float e = df * W0[jj] + m * W1[jj] + eb[jj];
        s1 += e; s2 += e * e;
    }
    float mean = s1 * (1.0f / DTS);
    float var = s2 * (1.0f / DTS) - mean * mean;
    float rstd = rsqrtf(var + EPS);
    float acc = 0.f;
    for (int jj = 0; jj < DTS; jj++) {
        float e = df * W0[jj] + m * W1[jj] + eb[jj];
        acc += geluf((e - mean) * rstd * gg[jj] + bb[jj]);
    }
    g_lut[idx] = acc * (1.0f / DTS);
}

// ---------------- pairwise mask ------------------------------------------------
__global__ void mask3_kernel(const float* __restrict__ ts) {
    int idx = blockIdx.x * blockDim.x + threadIdx.x;
    if (idx >= BSS) return;
    int k = idx % S;
    int q = (idx / S) % S;
    int b = idx / (S * S);
    float dt = ts[b * S + q] - ts[b * S + k];
    int dsel = (dt > 0.f) ? 2 : ((dt < 0.f) ? 0 : 1);
    float m = log1pf(fabsf(dt) * (1.0f / 3600.0f));
    float u = m * ((float)NLUT / MMAX);
    u = fminf(u, (float)NLUT - 1e-3f);
    u = fmaxf(u, 0.0f);
    int j = (int)u;
    float f = u - (float)j;
#pragma unroll
    for (int t = 0; t < T; t++) {
        const float* lp = g_lut + (size_t)(t * 3 + dsel) * (NLUT + 1) + j;
        g_mask3[(size_t)t * BSS + idx] = lp[0] + f * (lp[1] - lp[0]);
    }
}

// ---------------- tf32 GEMM: cp.async 3-stage, BK=32, ldmatrix A ---------------
// 8 warps as 2(M) x 4(N); warp tile 64 x (BN/4). NF = BN/32 fragments of 8 cols.
template <int ACT, int BN, int WMODE>
__global__ void __launch_bounds__(256) tgemm(
    const float* __restrict__ A, int lda, long sA,
    const float* __restrict__ Bm, int ldb, long sB,
    const float* __restrict__ bias, long sBias,
    float* __restrict__ C, float* __restrict__ Ctf, int ldc, long sC, int K) {
    constexpr int PA = 36, PB = BN + 8;
    constexpr int NF = BN / 32;
    extern __shared__ __align__(16) char smem_raw[];
    float* AsBase = (float*)smem_raw;               // 3 * 128*PA
    float* BsBase = AsBase + 3 * 128 * PA;          // 3 * 32*PB
    const int z = blockIdx.z;
    A += (size_t)z * sA; Bm += (size_t)z * sB; bias += (size_t)z * sBias;
    C += (size_t)z * sC;
    if (WMODE == 2) Ctf += (size_t)z * sC;
    const int tid = threadIdx.x;
    const int m0 = blockIdx.y * 128, n0 = blockIdx.x * BN;
    const int lane = tid & 31, wid = tid >> 5;
    const int warp_m = (wid & 1) * 64, warp_n = (wid >> 1) * (BN / 4);
    const int grp = lane >> 2, thr = lane & 3;
    // cp.async A: 128 rows x 32 cols / 256 thr = 4 cp16 each
    const int car = tid >> 1, cac = (tid & 1) * 16;
    const float* Asrc = A + (size_t)(m0 + car) * lda + cac;
    // cp.async B: 32 rows x BN
    const int cbr = tid >> 3;
    const int cbc = (BN == 128) ? ((tid & 7) * 16) : ((tid & 7) * 8);
    const float* Bsrc = Bm + (size_t)cbr * ldb + n0 + cbc;
    const uint32_t aDst = smem_u32(AsBase + car * PA + cac);
    const uint32_t bDst = smem_u32(BsBase + cbr * PB + cbc);
    constexpr uint32_t aStg = 128 * PA * 4;
    constexpr uint32_t bStg = 32 * PB * 4;
    constexpr int NB16 = (BN == 128) ? 4 : 2;

    const int kIters = K / 32;
#pragma unroll
    for (int s = 0; s < 2; s++) {
#pragma unroll
        for (int i = 0; i < 4; i++) cp16(aDst + s * aStg + i * 16, Asrc + s * 32 + i * 4);
#pragma unroll
        for (int i = 0; i < NB16; i++)
            cp16(bDst + s * bStg + i * 16, Bsrc + (size_t)(s * 32) * ldb + i * 4);
        cp_commit();
    }
    float c[4][NF][4];
#pragma unroll
    for (int i = 0; i < 4; i++)
#pragma unroll
        for (int j = 0; j < NF; j++)
#pragma unroll
            for (int l = 0; l < 4; l++) c[i][j][l] = 0.f;

    // ldmatrix lane addressing: rows (lane&7)+((lane>>3)&1)*8, cols (lane>>4)*4
    const uint32_t ldmRow = (lane & 7) + ((lane >> 3) & 1) * 8;
    const uint32_t ldmCol = (lane >> 4) * 4;
    const uint32_t aLdm = smem_u32(AsBase + (warp_m + ldmRow) * PA + ldmCol);

    int sCur = 0, sNext = 2;
    for (int i = 0; i < kIters; i++) {
        cp_wait<1>();
        __syncthreads();
        int kn = (i + 2) * 32;
        if (kn < K) {
#pragma unroll
            for (int u = 0; u < 4; u++) cp16(aDst + sNext * aStg + u * 16, Asrc + kn + u * 4);
#pragma unroll
            for (int u = 0; u < NB16; u++)
                cp16(bDst + sNext * bStg + u * 16, Bsrc + (size_t)kn * ldb + u * 4);
        }
        cp_commit();
        const float* Bs = BsBase + sCur * (32 * PB);
        const uint32_t aOff = aLdm + sCur * aStg;
#pragma unroll
        for (int kb = 0; kb < 32; kb += 8) {
            uint32_t af[4][4];
#pragma unroll
            for (int mf = 0; mf < 4; mf++)
                ldsm4(af[mf], aOff + (uint32_t)(mf * 16 * PA + kb) * 4);
#pragma unroll
            for (int nf = 0; nf < NF; nf++) {
                int c0 = warp_n + nf * 8;
                uint32_t b0 = __float_as_uint(Bs[(kb + thr) * PB + c0 + grp]);
                uint32_t b1 = __float_as_uint(Bs[(kb + thr + 4) * PB + c0 + grp]);
#pragma unroll
                for (int mf = 0; mf < 4; mf++)
                    mma_tf32(c[mf][nf], af[mf][0], af[mf][1], af[mf][2], af[mf][3], b0, b1);
            }
        }
        sCur = (sCur == 2) ? 0 : sCur + 1;
        sNext = (sNext == 2) ? 0 : sNext + 1;
    }
#pragma unroll
    for (int mf = 0; mf < 4; mf++)
#pragma unroll
        for (int nf = 0; nf < NF; nf++) {
            int row = m0 + warp_m + mf * 16 + grp;
            int col = n0 + warp_n + nf * 8 + thr * 2;
            float bx = bias[col], by = bias[col + 1];
            float* cr = c[mf][nf];
            float v0 = cr[0] + bx, v1 = cr[1] + by;
            float v2 = cr[2] + bx, v3 = cr[3] + by;
            if (ACT == 1) { v0 = geluf(v0); v1 = geluf(v1); v2 = geluf(v2); v3 = geluf(v3); }
            float* p0 = C + (size_t)row * ldc + col;
            float* p1 = C + (size_t)(row + 8) * ldc + col;
            if (WMODE == 1) {
                *(float2*)p0 = make_float2(tf32r(v0), tf32r(v1));
                *(float2*)p1 = make_float2(tf32r(v2), tf32r(v3));
            } else {
                *(float2*)p0 = make_float2(v0, v1);
                *(float2*)p1 = make_float2(v2, v3);
                if (WMODE == 2) {
                    *(float2*)(Ctf + (size_t)row * ldc + col) = make_float2(tf32r(v0), tf32r(v1));
                    *(float2*)(Ctf + (size_t)(row + 8) * ldc + col) = make_float2(tf32r(v2), tf32r(v3));
                }
            }
        }
}

// ---------------- fused flash attention (ldmatrix Q/K/P) -----------------------
// grid (4 q-tiles, z = t*32 + b*8 + h); 512 threads = 16 warps (4M x 4N).
namespace fa {
constexpr int PQ = 68, PVp = 72, PP = 132;
constexpr int SZ_Q = 128 * PQ;
constexpr int SZ_K = 128 * PQ;
constexpr int SZ_V = 128 * PVp;
constexpr int SZ_P = 128 * PP;
constexpr int SMEM_FLOATS = SZ_Q + 2 * SZ_K + SZ_V + SZ_P + 2 * 512;
constexpr int SMEM_BYTES = SMEM_FLOATS * 4;  // 213 KB
}

__global__ void __launch_bounds__(512) attn_fused(
    const float* __restrict__ qkvBase, const float* __restrict__ maskBase,
    float* __restrict__ OBase) {
    using namespace fa;
    extern __shared__ __align__(16) float sm[];
    float* Qs = sm;
    float* Kb[2] = {Qs + SZ_Q, Qs + SZ_Q + SZ_K};
    float* Vs = Kb[1] + SZ_K;
    float* Ps = Vs + SZ_V;
    float* redM = Ps + SZ_P;
    float* redS = redM + 512;

    const int tid = threadIdx.x;
    const int z = blockIdx.y;
    const int t = z >> 5, bh = z & 31;
    const int b = bh >> 3, h = bh & 7;
    const float* qkv = qkvBase + (size_t)t * MTOK * H3;
    const int q0 = blockIdx.x * 128;
    const int lane = tid & 31, wid = tid >> 5;
    const int warp_m = wid & 3, warp_n = wid >> 2;
    const int grp = lane >> 2, thr = lane & 3;

    const int lrow = tid >> 2, lcol = (tid & 3) * 16;
    {
        const float* Qsrc = qkv + (size_t)(b * S + q0 + lrow) * H3 + h * DH + lcol;
        uint32_t d = smem_u32(Qs + lrow * PQ + lcol);
#pragma unroll
        for (int i = 0; i < 4; i++) cp16(d + 16 * i, Qsrc + 4 * i);
    }
#define CPK(KC, BUF)                                                              \
    {                                                                             \
        const float* src = qkv + (size_t)(b * S + (KC) * 128 + lrow) * H3 + H + h * DH + lcol; \
        uint32_t d = smem_u32((BUF) + lrow * PQ + lcol);                          \
        _Pragma("unroll") for (int i = 0; i < 4; i++) cp16(d + 16 * i, src + 4 * i); \
    }
    CPK(0, Kb[0]); cp_commit();
    CPK(1, Kb[1]); cp_commit();

    const float* mb = maskBase ? (maskBase + (size_t)t * BSS + (size_t)b * S * S) : nullptr;

    // ldmatrix lane addressing
    const uint32_t ldmRow = (lane & 7) + ((lane >> 3) & 1) * 8;
    const uint32_t ldmCol = (lane >> 4) * 4;
    const uint32_t qLdm = smem_u32(Qs + (warp_m * 32 + ldmRow) * PQ + ldmCol);
    const uint32_t pLdm = smem_u32(Ps + (warp_m * 32 + ldmRow) * PP + ldmCol);
    const uint32_t kLdmL = (uint32_t)((warp_n * 32 + ldmRow) * PQ + ldmCol) * 4;

    float o[2][2][4];
#pragma unroll
    for (int i = 0; i < 2; i++)
#pragma unroll
        for (int j = 0; j < 2; j++)
#pragma unroll
            for (int l = 0; l < 4; l++) o[i][j][l] = 0.f;
    float mrow[2][2] = {{-1e30f, -1e30f}, {-1e30f, -1e30f}};
    float lsum[2][2] = {{0.f, 0.f}, {0.f, 0.f}};

    for (int kc = 0; kc < 4; kc++) {
        {   // V chunk (single buffer; consumed after the stats phase)
            const float* src = qkv + (size_t)(b * S + kc * 128 + lrow) * H3 + 2 * H + h * DH + lcol;
            uint32_t d = smem_u32(Vs + lrow * PVp + lcol);
#pragma unroll
            for (int i = 0; i < 4; i++) cp16(d + 16 * i, src + 4 * i);
            cp_commit();
        }
        if (kc == 0) { cp_wait<2>(); __syncthreads(); }  // Q + K0 visible

        const float* Ks = Kb[kc & 1];
        const uint32_t kLdm = smem_u32(Ks) + kLdmL;
        float sc[2][4][4];
#pragma unroll
        for (int i = 0; i < 2; i++)
#pragma unroll
            for (int j = 0; j < 4; j++)
#pragma unroll
                for (int l = 0; l < 4; l++) sc[i][j][l] = 0.f;

#pragma unroll
        for (int kb = 0; kb < 64; kb += 8) {
            uint32_t qf[2][4];
#pragma unroll
            for (int mf = 0; mf < 2; mf++)
                ldsm4(qf[mf], qLdm + (uint32_t)(mf * 16 * PQ + kb) * 4);
            // K x4: {b0(nfA), b0(nfB), b1(nfA), b1(nfB)} per 16-row pair
            uint32_t kf[2][4];
#pragma unroll
            for (int p = 0; p < 2; p++)
                ldsm4(kf[p], kLdm + (uint32_t)(p * 16 * PQ + kb) * 4);
#pragma unroll
            for (int nf = 0; nf < 4; nf++) {
                uint32_t b0 = kf[nf >> 1][nf & 1];
                uint32_t b1 = kf[nf >> 1][2 + (nf & 1)];
                mma_tf32(sc[0][nf], qf[0][0], qf[0][1], qf[0][2], qf[0][3], b0, b1);
                mma_tf32(sc[1][nf], qf[1][0], qf[1][1], qf[1][2], qf[1][3], b0, b1);
            }
        }

        // scale + mask + partial row max over this warp's 32 cols
        float pmax[2][2] = {{-1e30f, -1e30f}, {-1e30f, -1e30f}};
#pragma unroll
        for (int mf = 0; mf < 2; mf++) {
            int qr = q0 + warp_m * 32 + mf * 16 + grp;
#pragma unroll
            for (int nf = 0; nf < 4; nf++) {
                int kcol = kc * 128 + warp_n * 32 + nf * 8 + thr * 2;
                float e0 = sc[mf][nf][0] * 0.125f, e1 = sc[mf][nf][1] * 0.125f;
                float e2 = sc[mf][nf][2] * 0.125f, e3 = sc[mf][nf][3] * 0.125f;
                if (mb) {
                    float2 ma = *(const float2*)(mb + (size_t)qr * S + kcol);
                    float2 mc = *(const float2*)(mb + (size_t)(qr + 8) * S + kcol);
                    e0 += ma.x; e1 += ma.y; e2 += mc.x; e3 += mc.y;
                }
                sc[mf][nf][0] = e0; sc[mf][nf][1] = e1;
                sc[mf][nf][2] = e2; sc[mf][nf][3] = e3;
                pmax[mf][0] = fmaxf(pmax[mf][0], fmaxf(e0, e1));
                pmax[mf][1] = fmaxf(pmax[mf][1], fmaxf(e2, e3));
            }
        }
#pragma unroll
        for (int mf = 0; mf < 2; mf++)
#pragma unroll
            for (int r2 = 0; r2 < 2; r2++) {
                float v = pmax[mf][r2];
                v = fmaxf(v, __shfl_xor_sync(0xffffffffu, v, 1));
                v = fmaxf(v, __shfl_xor_sync(0xffffffffu, v, 2));
                pmax[mf][r2] = v;
            }
        if (thr == 0) {
#pragma unroll
            for (int mf = 0; mf < 2; mf++)
#pragma unroll
                for (int r2 = 0; r2 < 2; r2++) {
                    int r = warp_m * 32 + mf * 16 + grp + r2 * 8;
                    redM[r * 4 + warp_n] = pmax[mf][r2];
                }
        }
        __syncthreads();  // (a) max partials visible; all S-MMA reads of Kb done

        float alpha[2][2];
#pragma unroll
        for (int mf = 0; mf < 2; mf++)
#pragma unroll
            for (int r2 = 0; r2 < 2; r2++) {
                int r = warp_m * 32 + mf * 16 + grp + r2 * 8;
                float mc = fmaxf(fmaxf(redM[r * 4 + 0], redM[r * 4 + 1]),
                                 fmaxf(redM[r * 4 + 2], redM[r * 4 + 3]));
                float mn = fmaxf(mrow[mf][r2], mc);
                alpha[mf][r2] = expf(mrow[mf][r2] - mn);
                mrow[mf][r2] = mn;
            }

        // P = exp(s - m), tf32-rounded into smem; accumulate partial sums
        float psum[2][2] = {{0.f, 0.f}, {0.f, 0.f}};
#pragma unroll
        for (int mf = 0; mf < 2; mf++) {
            int pr = warp_m * 32 + mf * 16 + grp;
#pragma unroll
            for (int nf = 0; nf < 4; nf++) {
                int pc = warp_n * 32 + nf * 8 + thr * 2;
                float p0 = expf(sc[mf][nf][0] - mrow[mf][0]);
                float p1 = expf(sc[mf][nf][1] - mrow[mf][0]);
                float p2 = expf(sc[mf][nf][2] - mrow[mf][1]);
                float p3 = expf(sc[mf][nf][3] - mrow[mf][1]);
                psum[mf][0] += p0 + p1;
                psum[mf][1] += p2 + p3;
                *(float2*)&Ps[pr * PP + pc] = make_float2(tf32r(p0), tf32r(p1));
                *(float2*)&Ps[(pr + 8) * PP + pc] = make_float2(tf32r(p2), tf32r(p3));
            }
        }
#pragma unroll
        for (int mf = 0; mf < 2; mf++)
#pragma unroll
            for (int r2 = 0; r2 < 2; r2++) {
                float v = psum[mf][r2];
                v += __shfl_xor_sync(0xffffffffu, v, 1);
                v += __shfl_xor_sync(0xffffffffu, v, 2);
                psum[mf][r2] = v;
            }
        if (thr == 0) {
#pragma unroll
            for (int mf = 0; mf < 2; mf++)
#pragma unroll
                for (int r2 = 0; r2 < 2; r2++) {
                    int r = warp_m * 32 + mf * 16 + grp + r2 * 8;
                    redS[r * 4 + warp_n] = psum[mf][r2];
                }
        }
        // rescale O by alpha
#pragma unroll
        for (int mf = 0; mf < 2; mf++)
#pragma unroll
            for (int nf = 0; nf < 2; nf++) {
                o[mf][nf][0] *= alpha[mf][0]; o[mf][nf][1] *= alpha[mf][0];
                o[mf][nf][2] *= alpha[mf][1]; o[mf][nf][3] *= alpha[mf][1];
            }
        cp_wait<0>();      // V_kc (and K_{kc+1}) complete
        __syncthreads();   // (b) P + sum partials + V visible

#pragma unroll
        for (int mf = 0; mf < 2; mf++)
#pragma unroll
            for (int r2 = 0; r2 < 2; r2++) {
                int r = warp_m * 32 + mf * 16 + grp + r2 * 8;
                float srow = redS[r * 4 + 0] + redS[r * 4 + 1] + redS[r * 4 + 2] + redS[r * 4 + 3];
                lsum[mf][r2] = alpha[mf][r2] * lsum[mf][r2] + srow;
            }

        // O += P * V
#pragma unroll
        for (int kb = 0; kb < 128; kb += 8) {
            uint32_t pf[2][4];
#pragma unroll
            for (int mf = 0; mf < 2; mf++)
                ldsm4(pf[mf], pLdm + (uint32_t)(mf * 16 * PP + kb) * 4);
#pragma unroll
            for (int nf = 0; nf < 2; nf++) {
                int c0 = warp_n * 16 + nf * 8;
                uint32_t b0 = __float_as_uint(Vs[(kb + thr) * PVp + c0 + grp]);
                uint32_t b1 = __float_as_uint(Vs[(kb + thr + 4) * PVp + c0 + grp]);
                mma_tf32(o[0][nf], pf[0][0], pf[0][1], pf[0][2], pf[0][3], b0, b1);
                mma_tf32(o[1][nf], pf[1][0], pf[1][1], pf[1][2], pf[1][3], b0, b1);
            }
        }
        __syncthreads();   // (c) PV reads of Ps/Vs done before next chunk overwrites
        if (kc < 2) { CPK(kc + 2, Kb[kc & 1]); cp_commit(); }
    }
#undef CPK

    // epilogue: O / l, tf32-round, store
    float* O = OBase + (size_t)t * MTOK * H;
    float inv[2][2];
#pragma unroll
    for (int mf = 0; mf < 2; mf++)
#pragma unroll
        for (int r2 = 0; r2 < 2; r2++) inv[mf][r2] = 1.0f / lsum[mf][r2];
#pragma unroll
    for (int mf = 0; mf < 2; mf++)
#pragma unroll
        for (int nf = 0; nf < 2; nf++) {
            int q = q0 + warp_m * 32 + mf * 16 + grp;
            int col = h * DH + warp_n * 16 + nf * 8 + thr * 2;
            float* cr = o[mf][nf];
            *(float2*)(O + (size_t)(b * S + q) * H + col) =
                make_float2(tf32r(cr[0] * inv[mf][0]), tf32r(cr[1] * inv[mf][0]));
            *(float2*)(O + (size_t)(b * S + q + 8) * H + col) =
                make_float2(tf32r(cr[2] * inv[mf][1]), tf32r(cr[3] * inv[mf][1]));
        }
}

// ---------------- layernorm over 512; TFM: 0 fp32, 1 rounded, 2 dual -----------
template <bool ADD, bool GELU, int TFM>
__global__ void ln512(const float* __restrict__ X, const float* __restrict__ R,
                      const float* __restrict__ g, const float* __restrict__ bt,
                      float* __restrict__ out, float* __restrict__ out2) {
    int row = blockIdx.x, tid = threadIdx.x;
    const float* x = X + (size_t)row * H;
    float v[4];
    float s = 0.f, sq = 0.f;
#pragma unroll
    for (int i = 0; i < 4; i++) {
        int c = tid + 128 * i;
        float t = x[c];
        if (ADD) t += R[(size_t)row * H + c];
        v[i] = t; s += t; sq += t * t;
    }
#pragma unroll
    for (int o = 16; o; o >>= 1) {
        s += __shfl_xor_sync(0xffffffffu, s, o);
        sq += __shfl_xor_sync(0xffffffffu, sq, o);
    }
    __shared__ float shs[4], shq[4];
    int warp = tid >> 5, lane = tid & 31;
    if (lane == 0) { shs[warp] = s; shq[warp] = sq; }
    __syncthreads();
    s = shs[0] + shs[1] + shs[2] + shs[3];
    sq = shq[0] + shq[1] + shq[2] + shq[3];
    float mean = s * (1.0f / H);
    float var = sq * (1.0f / H) - mean * mean;
    float rstd = rsqrtf(var + EPS);
#pragma unroll
    for (int i = 0; i < 4; i++) {
        int c = tid + 128 * i;
        float y = (v[i] - mean) * rstd * g[c] + bt[c];
        if (GELU) y = geluf(y);
        if (TFM == 1) out[(size_t)row * H + c] = tf32r(y);
        else out[(size_t)row * H + c] = y;
        if (TFM == 2) out2[(size_t)row * H + c] = tf32r(y);
    }
}

// ---------------- mixer logits + softmax + weighted sum ------------------------
__global__ void mix_weighted_kernel(const float* __restrict__ W2,
                                    const float* __restrict__ b2) {
    int tok = blockIdx.x, tid = threadIdx.x;
    float p0 = 0.f, p1 = 0.f, p2 = 0.f;
    for (int i = tid; i < H; i += 128) {
        float mv = g_m[(size_t)tok * H + i];
        p0 += mv * W2[i * 3 + 0];
        p1 += mv * W2[i * 3 + 1];
        p2 += mv * W2[i * 3 + 2];
    }
    __shared__ float red0[128], red1[128], red2[128];
    red0[tid] = p0; red1[tid] = p1; red2[tid] = p2;
    __syncthreads();
    for (int s = 64; s > 0; s >>= 1) {
        if (tid < s) { red0[tid] += red0[tid + s]; red1[tid] += red1[tid + s]; red2[tid] += red2[tid + s]; }
        __syncthreads();
    }
    __shared__ float mix[3];
    if (tid == 0) {
        float l0 = red0[0] + b2[0], l1 = red1[0] + b2[1], l2 = red2[0] + b2[2];
        float mx = fmaxf(l0, fmaxf(l1, l2));
        float e0 = expf(l0 - mx), e1 = expf(l1 - mx), e2 = expf(l2 - mx);
        float inv = 1.0f / (e0 + e1 + e2);
        mix[0] = e0 * inv; mix[1] = e1 * inv; mix[2] = e2 * inv;
    }
    __syncthreads();
    float w0 = mix[0], w1 = mix[1], w2 = mix[2];
    for (int c = tid; c < H; c += 128) {
        const float* cb = g_combined + (size_t)tok * H3;
        float w = w0 * cb[c] + w1 * cb[H + c] + w2 * cb[2 * H + c];
        g_weighted[(size_t)tok * H + c] = w;
        g_weighted_tf[(size_t)tok * H + c] = tf32r(w);
    }
}

// -----------------------------------------------------------------------------
static float* symaddr(const void* sym) {
    void* p = nullptr;
    cudaGetSymbolAddress(&p, sym);
    return (float*)p;
}

extern "C" void kernel_launch(void* const* d_in, const int* in_sizes, int n_in,
                              void* d_out, int out_size) {
    const float* x          = (const float*)d_in[0];
    const float* ts         = (const float*)d_in[1];
    const float* enc_W      = (const float*)d_in[2];
    const float* enc_b      = (const float*)d_in[3];
    const float* enc_ln_g   = (const float*)d_in[4];
    const float* enc_ln_b   = (const float*)d_in[5];
    const float* qkv_W      = (const float*)d_in[6];
    const float* qkv_b      = (const float*)d_in[7];
    const float* attn_out_W = (const float*)d_in[8];
    const float* attn_out_b = (const float*)d_in[9];
    const float* mixer_W1   = (const float*)d_in[10];
    const float* mixer_b1   = (const float*)d_in[11];
    const float* mixer_ln_g = (const float*)d_in[12];
    const float* mixer_ln_b = (const float*)d_in[13];
    const float* mixer_W2   = (const float*)d_in[14];
    const float* mixer_b2   = (const float*)d_in[15];
    const float* el_qkv_W   = (const float*)d_in[16];
    const float* el_qkv_b   = (const float*)d_in[17];
    const float* el_out_W   = (const float*)d_in[18];
    const float* el_out_b   = (const float*)d_in[19];
    const float* el_ln1_g   = (const float*)d_in[20];
    const float* el_ln1_b   = (const float*)d_in[21];
    const float* el_ff_W1   = (const float*)d_in[22];
    const float* el_ff_b1   = (const float*)d_in[23];
    const float* el_ff_W2   = (const float*)d_in[24];
    const float* el_ff_b2   = (const float*)d_in[25];
    const float* el_ln2_g   = (const float*)d_in[26];
    const float* el_ln2_b   = (const float*)d_in[27];
    const float* op_W       = (const float*)d_in[28];
    const float* op_b       = (const float*)d_in[29];
    const float* op_ln_g    = (const float*)d_in[30];
    const float* op_ln_b    = (const float*)d_in[31];
    float* out = (float*)d_out;

    float* qkv3     = symaddr(g_qkv3);
    float* attn_o3  = symaddr(g_attn_o3);
    float* combined = symaddr(g_combined);
    float* combtf   = symaddr(g_combined_tf);
    float* mask3    = symaddr(g_mask3);
    float* mbuf     = symaddr(g_m);
    float* big      = symaddr(g_big);
    float* weighted = symaddr(g_weighted);
    float* wtdtf    = symaddr(g_weighted_tf);
    float* h1       = symaddr(g_h1);
    float* h1tf     = symaddr(g_h1tf);
    float* h2       = symaddr(g_h2);
    float* xtf      = symaddr(g_xtf);
    float* w_qkv = symaddr(g_w_qkv); float* w_ao = symaddr(g_w_ao);
    float* w_m1  = symaddr(g_w_m1);  float* w_eq = symaddr(g_w_eq);
    float* w_eo  = symaddr(g_w_eo);  float* w_f1 = symaddr(g_w_f1);
    float* w_f2  = symaddr(g_w_f2);  float* w_op = symaddr(g_w_op);

    constexpr int SM_G128 = 3 * (128 * 36 + 32 * 136) * 4;  // 107520
    constexpr int SM_G64  = 3 * (128 * 36 + 32 * 72) * 4;   // 82944
    cudaFuncSetAttribute(tgemm<0, 128, 1>, cudaFuncAttributeMaxDynamicSharedMemorySize, SM_G128);
    cudaFuncSetAttribute(tgemm<0, 128, 2>, cudaFuncAttributeMaxDynamicSharedMemorySize, SM_G128);
    cudaFuncSetAttribute(tgemm<1, 128, 1>, cudaFuncAttributeMaxDynamicSharedMemorySize, SM_G128);
    cudaFuncSetAttribute(tgemm<0, 64, 0>, cudaFuncAttributeMaxDynamicSharedMemorySize, SM_G64);
    cudaFuncSetAttribute(attn_fused, cudaFuncAttributeMaxDynamicSharedMemorySize, fa::SMEM_BYTES);

    // 0. one-launch tf32 pre-rounding (x + 8 weight tensors)
    {
        RtArgs a;
        a.src[0] = (const float4*)x;          a.dst[0] = (float4*)xtf;
        a.src[1] = (const float4*)qkv_W;      a.dst[1] = (float4*)w_qkv;
        a.src[2] = (const float4*)attn_out_W; a.dst[2] = (float4*)w_ao;
        a.src[3] = (const float4*)mixer_W1;   a.dst[3] = (float4*)w_m1;
        a.src[4] = (const float4*)el_qkv_W;   a.dst[4] = (float4*)w_eq;
        a.src[5] = (const float4*)el_out_W;   a.dst[5] = (float4*)w_eo;
        a.src[6] = (const float4*)el_ff_W1;   a.dst[6] = (float4*)w_f1;
        a.src[7] = (const float4*)el_ff_W2;   a.dst[7] = (float4*)w_f2;
        a.src[8] = (const float4*)op_W;       a.dst[8] = (float4*)w_op;
        roundtf_all<<<(2097152 + 255) / 256, 256>>>(a);
    }

    // 1. LUT + masks
    build_lut_kernel<<<(T * 3 * (NLUT + 1) + 127) / 128, 128>>>(enc_W, enc_b, enc_ln_g, enc_ln_b);
    mask3_kernel<<<(BSS + 255) / 256, 256>>>(ts);

    // 2. per-timescale MHA (z-batched over t), attention fully fused
    tgemm<0, 128, 1><<<dim3(H3 / 128, MTOK / 128, 3), 256, SM_G128>>>(
        xtf, H, 0L, w_qkv, H3, (long)H * H3, qkv_b, (long)H3,
        qkv3, nullptr, H3, (long)MTOK * H3, H);
    attn_fused<<<dim3(4, 96), 512, fa::SMEM_BYTES>>>(qkv3, mask3, attn_o3);
    tgemm<0, 128, 2><<<dim3(H / 128, MTOK / 128, 3), 256, SM_G128>>>(
        attn_o3, H, (long)MTOK * H, w_ao, H, (long)H * H, attn_out_b, (long)H,
        combined, combtf, H3, (long)H, H);

    // 3. mixer
    tgemm<0, 64, 0><<<dim3(H / 64, MTOK / 128, 1), 256, SM_G64>>>(
        combtf, H3, 0L, w_m1, H, 0L, mixer_b1, 0L, big, nullptr, H, 0L, H3);
    ln512<false, true, 0><<<MTOK, 128>>>(big, nullptr, mixer_ln_g, mixer_ln_b, mbuf, nullptr);
    mix_weighted_kernel<<<MTOK, 128>>>(mixer_W2, mixer_b2);

    // 4. transformer encoder layer
    tgemm<0, 128, 1><<<dim3(H3 / 128, MTOK / 128, 1), 256, SM_G128>>>(
        wtdtf, H, 0L, w_eq, H3, 0L, el_qkv_b, 0L, qkv3, nullptr, H3, 0L, H);
    attn_fused<<<dim3(4, 32), 512, fa::SMEM_BYTES>>>(qkv3, nullptr, attn_o3);
    tgemm<0, 64, 0><<<dim3(H / 64, MTOK / 128, 1), 256, SM_G64>>>(
        attn_o3, H, 0L, w_eo, H, 0L, el_out_b, 0L, mbuf, nullptr, H, 0L, H);
    ln512<true, false, 2><<<MTOK, 128>>>(weighted, mbuf, el_ln1_g, el_ln1_b, h1, h1tf);
    tgemm<1, 128, 1><<<dim3(H4 / 128, MTOK / 128, 1), 256, SM_G128>>>(
        h1tf, H, 0L, w_f1, H4, 0L, el_ff_b1, 0L, big, nullptr, H4, 0L, H);
    tgemm<0, 64, 0><<<dim3(H / 64, MTOK / 128, 1), 256, SM_G64>>>(
        big, H4, 0L, w_f2, H, 0L, el_ff_b2, 0L, mbuf, nullptr, H, 0L, H4);
    ln512<true, false, 1><<<MTOK, 128>>>(h1, mbuf, el_ln2_g, el_ln2_b, h2, nullptr);

    // 5. output projection + final LN
    tgemm<0, 64, 0><<<dim3(H / 64, MTOK / 128, 1), 256, SM_G64>>>(
        h2, H, 0L, w_op, H, 0L, op_b, 0L, mbuf, nullptr, H, 0L, H);
    ln512<false, false, 0><<<MTOK, 128>>>(mbuf, nullptr, op_ln_g, op_ln_b, out, nullptr);
}

// round 9
// speedup vs baseline: 1.0114x; 1.0114x over previous
#include <cuda_runtime.h>
#include <cstdint>

#define DI __device__ __forceinline__

namespace {
constexpr int B = 4, S = 512, H = 512, NH = 8, T = 3, DH = 64, DTS = 170;
constexpr int MTOK = B * S;
constexpr int H3 = 3 * H;
constexpr int H4 = 4 * H;
constexpr int BSS = B * S * S;
constexpr float EPS = 1e-5f;
constexpr int NLUT = 16384;
constexpr float MMAX = 5.6400f;
}

// ---------------- scratch ------------------------------------------------------
__device__ float g_qkv3[3 * MTOK * H3];
__device__ float g_attn_o3[3 * MTOK * H];
__device__ float g_combined[MTOK * H3];
__device__ float g_combined_tf[MTOK * H3];
__device__ float g_mask3[T * BSS];
__device__ float g_m[MTOK * H];
__device__ float g_big[MTOK * H4];
__device__ float g_weighted[MTOK * H];
__device__ float g_weighted_tf[MTOK * H];
__device__ float g_h1[MTOK * H];
__device__ float g_h1tf[MTOK * H];
__device__ float g_h2[MTOK * H];
__device__ float g_xtf[MTOK * H];
__device__ float g_lut[T * 3 * (NLUT + 1)];
// tf32 weight copies
__device__ float g_w_qkv[3 * H * H3];
__device__ float g_w_ao[3 * H * H];
__device__ float g_w_m1[H3 * H];
__device__ float g_w_eq[H * H3];
__device__ float g_w_eo[H * H];
__device__ float g_w_f1[H * H4];
__device__ float g_w_f2[H4 * H];
__device__ float g_w_op[H * H];

DI float geluf(float x) { return 0.5f * x * (1.0f + erff(x * 0.7071067811865475f)); }

DI uint32_t tf32cvt(float x) {
    uint32_t r;
    asm("cvt.rna.tf32.f32 %0, %1;" : "=r"(r) : "f"(x));
    return r;
}
DI float tf32r(float x) { return __uint_as_float(tf32cvt(x)); }

DI void mma_tf32(float* c, uint32_t a0, uint32_t a1, uint32_t a2, uint32_t a3,
                 uint32_t b0, uint32_t b1) {
    asm volatile(
        "mma.sync.aligned.m16n8k8.row.col.f32.tf32.tf32.f32 "
        "{%0,%1,%2,%3}, {%4,%5,%6,%7}, {%8,%9}, {%0,%1,%2,%3};"
        : "+f"(c[0]), "+f"(c[1]), "+f"(c[2]), "+f"(c[3])
        : "r"(a0), "r"(a1), "r"(a2), "r"(a3), "r"(b0), "r"(b1));
}

DI void ldsm4(uint32_t* r, uint32_t addr) {
    asm volatile("ldmatrix.sync.aligned.m8n8.x4.shared.b16 {%0,%1,%2,%3}, [%4];"
                 : "=r"(r[0]), "=r"(r[1]), "=r"(r[2]), "=r"(r[3]) : "r"(addr));
}

DI uint32_t smem_u32(const void* p) { return (uint32_t)__cvta_generic_to_shared(p); }
DI void cp16(uint32_t dst, const void* src) {
    asm volatile("cp.async.cg.shared.global [%0], [%1], 16;" :: "r"(dst), "l"(src));
}
DI void cp_commit() { asm volatile("cp.async.commit_group;"); }
template <int N> DI void cp_wait() { asm volatile("cp.async.wait_group %0;" :: "n"(N)); }

// ---------------- consolidated tf32 rounding (9 segments, one launch) ----------
struct RtArgs {
    const float4* src[9];
    float4* dst[9];
};
__global__ void roundtf_all(RtArgs a) {
    constexpr int bnd[10] = {
        0,
        262144,    // x          : 1048576 f
        851968,    // qkv_W      : +589824
        1048576,   // attn_out_W : +196608
        1245184,   // mixer_W1   : +196608
        1441792,   // el_qkv_W   : +196608
        1507328,   // el_out_W   : +65536
        1769472,   // el_ff_W1   : +262144
        2031616,   // el_ff_W2   : +262144
        2097152    // op_W       : +65536
    };
    int i = blockIdx.x * blockDim.x + threadIdx.x;
    if (i >= bnd[9]) return;
#pragma unroll
    for (int s = 0; s < 9; s++) {
        if (i >= bnd[s] && i < bnd[s + 1]) {
            int j = i - bnd[s];
            float4 v = a.src[s][j];
            float4 o;
            o.x = tf32r(v.x); o.y = tf32r(v.y); o.z = tf32r(v.z); o.w = tf32r(v.w);
            a.dst[s][j] = o;
            return;
        }
    }
}

// ---------------- LUT builder --------------------------------------------------
__global__ void build_lut_kernel(const float* __restrict__ encW,
                                 const float* __restrict__ encB,
                                 const float* __restrict__ lng,
                                 const float* __restrict__ lnb) {
    int idx = blockIdx.x * blockDim.x + threadIdx.x;
    const int total = T * 3 * (NLUT + 1);
    if (idx >= total) return;
    int j = idx % (NLUT + 1);
    int d = (idx / (NLUT + 1)) % 3;
    int t = idx / (3 * (NLUT + 1));
    float df = (float)(d - 1);
    float scale = (t == 0) ? 1.0f : ((t == 1) ? 0.1f : 0.01f);
    float m = (MMAX / NLUT) * (float)j * scale;
    const float* W0 = encW + t * 2 * DTS;
    const float* W1 = W0 + DTS;
    const float* eb = encB + t * DTS;
    const float* gg = lng + t * DTS;
    const float* bb = lnb + t * DTS;
    float s1 = 0.f, s2 = 0.f;
    for (int jj = 0; jj < DTS; jj++) {
        float e = df * W0[jj] + m * W1[jj] + eb[jj];
        s1 += e; s2 += e * e;
    }
    float mean = s1 * (1.0f / DTS);
    float var = s2 * (1.0f / DTS) - mean * mean;
    float rstd = rsqrtf(var + EPS);
    float acc = 0.f;
    for (int jj = 0; jj < DTS; jj++) {
        float e = df * W0[jj] + m * W1[jj] + eb[jj];
        acc += geluf((e - mean) * rstd * gg[jj] + bb[jj]);
    }
    g_lut[idx] = acc * (1.0f / DTS);
}

// ---------------- pairwise mask ------------------------------------------------
__global__ void mask3_kernel(const float* __restrict__ ts) {
    int idx = blockIdx.x * blockDim.x + threadIdx.x;
    if (idx >= BSS) return;
    int k = idx % S;
    int q = (idx / S) % S;
    int b = idx / (S * S);
    float dt = ts[b * S + q] - ts[b * S + k];
    int dsel = (dt > 0.f) ? 2 : ((dt < 0.f) ? 0 : 1);
    float m = log1pf(fabsf(dt) * (1.0f / 3600.0f));
    float u = m * ((float)NLUT / MMAX);
    u = fminf(u, (float)NLUT - 1e-3f);
    u = fmaxf(u, 0.0f);
    int j = (int)u;
    float f = u - (float)j;
#pragma unroll
    for (int t = 0; t < T; t++) {
        const float* lp = g_lut + (size_t)(t * 3 + dsel) * (NLUT + 1) + j;
        g_mask3[(size_t)t * BSS + idx] = lp[0] + f * (lp[1] - lp[0]);
    }
}

// ---------------- tf32 GEMM: cp.async 2-stage, BK=32, ldmatrix A ---------------
// 8 warps as 2(M) x 4(N); warp tile 64 x (BN/4). 2 CTAs/SM enforced.
template <int ACT, int BN, int WMODE>
__global__ void __launch_bounds__(256, 2) tgemm(
    const float* __restrict__ A, int lda, long sA,
    const float* __restrict__ Bm, int ldb, long sB,
    const float* __restrict__ bias, long sBias,
    float* __restrict__ C, float* __restrict__ Ctf, int ldc, long sC, int K) {
    constexpr int PA = 36, PB = BN + 8;
    constexpr int NF = BN / 32;
    extern __shared__ __align__(16) char smem_raw[];
    float* AsBase = (float*)smem_raw;               // 2 * 128*PA
    float* BsBase = AsBase + 2 * 128 * PA;          // 2 * 32*PB
    const int z = blockIdx.z;
    A += (size_t)z * sA; Bm += (size_t)z * sB; bias += (size_t)z * sBias;
    C += (size_t)z * sC;
    if (WMODE == 2) Ctf += (size_t)z * sC;
    const int tid = threadIdx.x;
    const int m0 = blockIdx.y * 128, n0 = blockIdx.x * BN;
    const int lane = tid & 31, wid = tid >> 5;
    const int warp_m = (wid & 1) * 64, warp_n = (wid >> 1) * (BN / 4);
    const int grp = lane >> 2, thr = lane & 3;
    const int car = tid >> 1, cac = (tid & 1) * 16;
    const float* Asrc = A + (size_t)(m0 + car) * lda + cac;
    const int cbr = tid >> 3;
    const int cbc = (BN == 128) ? ((tid & 7) * 16) : ((tid & 7) * 8);
    const float* Bsrc = Bm + (size_t)cbr * ldb + n0 + cbc;
    const uint32_t aDst = smem_u32(AsBase + car * PA + cac);
    const uint32_t bDst = smem_u32(BsBase + cbr * PB + cbc);
    constexpr uint32_t aStg = 128 * PA * 4;
    constexpr uint32_t bStg = 32 * PB * 4;
    constexpr int NB16 = (BN == 128) ? 4 : 2;

    const int kIters = K / 32;
    // prologue: stage 0
#pragma unroll
    for (int i = 0; i < 4; i++) cp16(aDst + i * 16, Asrc + i * 4);
#pragma unroll
    for (int i = 0; i < NB16; i++) cp16(bDst + i * 16, Bsrc + i * 4);
    cp_commit();

    float c[4][NF][4];
#pragma unroll
    for (int i = 0; i < 4; i++)
#pragma unroll
        for (int j = 0; j < NF; j++)
#pragma unroll
            for (int l = 0; l < 4; l++) c[i][j][l] = 0.f;

    const uint32_t ldmRow = (lane & 7) + ((lane >> 3) & 1) * 8;
    const uint32_t ldmCol = (lane >> 4) * 4;
    const uint32_t aLdm = smem_u32(AsBase + (warp_m + ldmRow) * PA + ldmCol);

    for (int i = 0; i < kIters; i++) {
        // prefetch next stage into the other buffer (freed by prior iter's trailing sync)
        int kn = (i + 1) * 32;
        if (kn < K) {
            uint32_t aD = aDst + ((i + 1) & 1) * aStg;
            uint32_t bD = bDst + ((i + 1) & 1) * bStg;
#pragma unroll
            for (int u = 0; u < 4; u++) cp16(aD + u * 16, Asrc + kn + u * 4);
#pragma unroll
            for (int u = 0; u < NB16; u++)
                cp16(bD + u * 16, Bsrc + (size_t)kn * ldb + u * 4);
        }
        cp_commit();
        cp_wait<1>();      // current stage (i) complete
        __syncthreads();
        const float* Bs = BsBase + (i & 1) * (32 * PB);
        const uint32_t aOff = aLdm + (i & 1) * aStg;
#pragma unroll
        for (int kb = 0; kb < 32; kb += 8) {
            uint32_t af[4][4];
#pragma unroll
            for (int mf = 0; mf < 4; mf++)
                ldsm4(af[mf], aOff + (uint32_t)(mf * 16 * PA + kb) * 4);
#pragma unroll
            for (int nf = 0; nf < NF; nf++) {
                int c0 = warp_n + nf * 8;
                uint32_t b0 = __float_as_uint(Bs[(kb + thr) * PB + c0 + grp]);
                uint32_t b1 = __float_as_uint(Bs[(kb + thr + 4) * PB + c0 + grp]);
#pragma unroll
                for (int mf = 0; mf < 4; mf++)
                    mma_tf32(c[mf][nf], af[mf][0], af[mf][1], af[mf][2], af[mf][3], b0, b1);
            }
        }
        __syncthreads();   // stage i fully consumed before iter i+1 overwrites it
    }
#pragma unroll
    for (int mf = 0; mf < 4; mf++)
#pragma unroll
        for (int nf = 0; nf < NF; nf++) {
            int row = m0 + warp_m + mf * 16 + grp;
            int col = n0 + warp_n + nf * 8 + thr * 2;
            float bx = bias[col], by = bias[col + 1];
            float* cr = c[mf][nf];
            float v0 = cr[0] + bx, v1 = cr[1] + by;
            float v2 = cr[2] + bx, v3 = cr[3] + by;
            if (ACT == 1) { v0 = geluf(v0); v1 = geluf(v1); v2 = geluf(v2); v3 = geluf(v3); }
            float* p0 = C + (size_t)row * ldc + col;
            float* p1 = C + (size_t)(row + 8) * ldc + col;
            if (WMODE == 1) {
                *(float2*)p0 = make_float2(tf32r(v0), tf32r(v1));
                *(float2*)p1 = make_float2(tf32r(v2), tf32r(v3));
            } else {
                *(float2*)p0 = make_float2(v0, v1);
                *(float2*)p1 = make_float2(v2, v3);
                if (WMODE == 2) {
                    *(float2*)(Ctf + (size_t)row * ldc + col) = make_float2(tf32r(v0), tf32r(v1));
                    *(float2*)(Ctf + (size_t)(row + 8) * ldc + col) = make_float2(tf32r(v2), tf32r(v3));
                }
            }
        }
}

// ---------------- fused flash attention (ldmatrix Q/K/P) -----------------------
// grid (4 q-tiles, z = t*32 + b*8 + h); 512 threads = 16 warps (4M x 4N).
namespace fa {
constexpr int PQ = 68, PVp = 72, PP = 132;
constexpr int SZ_Q = 128 * PQ;
constexpr int SZ_K = 128 * PQ;
constexpr int SZ_V = 128 * PVp;
constexpr int SZ_P = 128 * PP;
constexpr int SMEM_FLOATS = SZ_Q + 2 * SZ_K + SZ_V + SZ_P + 2 * 512;
constexpr int SMEM_BYTES = SMEM_FLOATS * 4;  // 213 KB
}

__global__ void __launch_bounds__(512) attn_fused(
    const float* __restrict__ qkvBase, const float* __restrict__ maskBase,
    float* __restrict__ OBase) {
    using namespace fa;
    extern __shared__ __align__(16) float sm[];
    float* Qs = sm;
    float* Kb[2] = {Qs + SZ_Q, Qs + SZ_Q + SZ_K};
    float* Vs = Kb[1] + SZ_K;
    float* Ps = Vs + SZ_V;
    float* redM = Ps + SZ_P;
    float* redS = redM + 512;

    const int tid = threadIdx.x;
    const int z = blockIdx.y;
    const int t = z >> 5, bh = z & 31;
    const int b = bh >> 3, h = bh & 7;
    const float* qkv = qkvBase + (size_t)t * MTOK * H3;
    const int q0 = blockIdx.x * 128;
    const int lane = tid & 31, wid = tid >> 5;
    const int warp_m = wid & 3, warp_n = wid >> 2;
    const int grp = lane >> 2, thr = lane & 3;

    const int lrow = tid >> 2, lcol = (tid & 3) * 16;
    {
        const float* Qsrc = qkv + (size_t)(b * S + q0 + lrow) * H3 + h * DH + lcol;
        uint32_t d = smem_u32(Qs + lrow * PQ + lcol);
#pragma unroll
        for (int i = 0; i < 4; i++) cp16(d + 16 * i, Qsrc + 4 * i);
    }
#define CPK(KC, BUF)                                                              \
    {                                                                             \
        const float* src = qkv + (size_t)(b * S + (KC) * 128 + lrow) * H3 + H + h * DH + lcol; \
        uint32_t d = smem_u32((BUF) + lrow * PQ + lcol);                          \
        _Pragma("unroll") for (int i = 0; i < 4; i++) cp16(d + 16 * i, src + 4 * i); \
    }
    CPK(0, Kb[0]); cp_commit();
    CPK(1, Kb[1]); cp_commit();

    const float* mb = maskBase ? (maskBase + (size_t)t * BSS + (size_t)b * S * S) : nullptr;

    const uint32_t ldmRow = (lane & 7) + ((lane >> 3) & 1) * 8;
    const uint32_t ldmCol = (lane >> 4) * 4;
    const uint32_t qLdm = smem_u32(Qs + (warp_m * 32 + ldmRow) * PQ + ldmCol);
    const uint32_t pLdm = smem_u32(Ps + (warp_m * 32 + ldmRow) * PP + ldmCol);
    const uint32_t kLdmL = (uint32_t)((warp_n * 32 + ldmRow) * PQ + ldmCol) * 4;

    float o[2][2][4];
#pragma unroll
    for (int i = 0; i < 2; i++)
#pragma unroll
        for (int j = 0; j < 2; j++)
#pragma unroll
            for (int l = 0; l < 4; l++) o[i][j][l] = 0.f;
    float mrow[2][2] = {{-1e30f, -1e30f}, {-1e30f, -1e30f}};
    float lsum[2][2] = {{0.f, 0.f}, {0.f, 0.f}};

    for (int kc = 0; kc < 4; kc++) {
        {   // V chunk (single buffer; consumed after the stats phase)
            const float* src = qkv + (size_t)(b * S + kc * 128 + lrow) * H3 + 2 * H + h * DH + lcol;
            uint32_t d = smem_u32(Vs + lrow * PVp + lcol);
#pragma unroll
            for (int i = 0; i < 4; i++) cp16(d + 16 * i, src + 4 * i);
            cp_commit();
        }
        if (kc == 0) { cp_wait<2>(); __syncthreads(); }  // Q + K0 visible

        const float* Ks = Kb[kc & 1];
        const uint32_t kLdm = smem_u32(Ks) + kLdmL;
        float sc[2][4][4];
#pragma unroll
        for (int i = 0; i < 2; i++)
#pragma unroll
            for (int j = 0; j < 4; j++)
#pragma unroll
                for (int l = 0; l < 4; l++) sc[i][j][l] = 0.f;

#pragma unroll
        for (int kb = 0; kb < 64; kb += 8) {
            uint32_t qf[2][4];
#pragma unroll
            for (int mf = 0; mf < 2; mf++)
                ldsm4(qf[mf], qLdm + (uint32_t)(mf * 16 * PQ + kb) * 4);
            uint32_t kf[2][4];
#pragma unroll
            for (int p = 0; p < 2; p++)
                ldsm4(kf[p], kLdm + (uint32_t)(p * 16 * PQ + kb) * 4);
#pragma unroll
            for (int nf = 0; nf < 4; nf++) {
                uint32_t b0 = kf[nf >> 1][nf & 1];
                uint32_t b1 = kf[nf >> 1][2 + (nf & 1)];
                mma_tf32(sc[0][nf], qf[0][0], qf[0][1], qf[0][2], qf[0][3], b0, b1);
                mma_tf32(sc[1][nf], qf[1][0], qf[1][1], qf[1][2], qf[1][3], b0, b1);
            }
        }

        float pmax[2][2] = {{-1e30f, -1e30f}, {-1e30f, -1e30f}};
#pragma unroll
        for (int mf = 0; mf < 2; mf++) {
            int qr = q0 + warp_m * 32 + mf * 16 + grp;
#pragma unroll
            for (int nf = 0; nf < 4; nf++) {
                int kcol = kc * 128 + warp_n * 32 + nf * 8 + thr * 2;
                float e0 = sc[mf][nf][0] * 0.125f, e1 = sc[mf][nf][1] * 0.125f;
                float e2 = sc[mf][nf][2] * 0.125f, e3 = sc[mf][nf][3] * 0.125f;
                if (mb) {
                    float2 ma = *(const float2*)(mb + (size_t)qr * S + kcol);
                    float2 mc = *(const float2*)(mb + (size_t)(qr + 8) * S + kcol);
                    e0 += ma.x; e1 += ma.y; e2 += mc.x; e3 += mc.y;
                }
                sc[mf][nf][0] = e0; sc[mf][nf][1] = e1;
                sc[mf][nf][2] = e2; sc[mf][nf][3] = e3;
                pmax[mf][0] = fmaxf(pmax[mf][0], fmaxf(e0, e1));
                pmax[mf][1] = fmaxf(pmax[mf][1], fmaxf(e2, e3));
            }
        }
#pragma unroll
        for (int mf = 0; mf < 2; mf++)
#pragma unroll
            for (int r2 = 0; r2 < 2; r2++) {
                float v = pmax[mf][r2];
                v = fmaxf(v, __shfl_xor_sync(0xffffffffu, v, 1));
                v = fmaxf(v, __shfl_xor_sync(0xffffffffu, v, 2));
                pmax[mf][r2] = v;
            }
        if (thr == 0) {
#pragma unroll
            for (int mf = 0; mf < 2; mf++)
#pragma unroll
                for (int r2 = 0; r2 < 2; r2++) {
                    int r = warp_m * 32 + mf * 16 + grp + r2 * 8;
                    redM[r * 4 + warp_n] = pmax[mf][r2];
                }
        }
        __syncthreads();  // (a) max partials visible; all S-MMA reads of Kb done

        float alpha[2][2];
#pragma unroll
        for (int mf = 0; mf < 2; mf++)
#pragma unroll
            for (int r2 = 0; r2 < 2; r2++) {
                int r = warp_m * 32 + mf * 16 + grp + r2 * 8;
                float mc = fmaxf(fmaxf(redM[r * 4 + 0], redM[r * 4 + 1]),
                                 fmaxf(redM[r * 4 + 2], redM[r * 4 + 3]));
                float mn = fmaxf(mrow[mf][r2], mc);
                alpha[mf][r2] = expf(mrow[mf][r2] - mn);
                mrow[mf][r2] = mn;
            }

        float psum[2][2] = {{0.f, 0.f}, {0.f, 0.f}};
#pragma unroll
        for (int mf = 0; mf < 2; mf++) {
            int pr = warp_m * 32 + mf * 16 + grp;
#pragma unroll
            for (int nf = 0; nf < 4; nf++) {
                int pc = warp_n * 32 + nf * 8 + thr * 2;
                float p0 = expf(sc[mf][nf][0] - mrow[mf][0]);
                float p1 = expf(sc[mf][nf][1] - mrow[mf][0]);
                float p2 = expf(sc[mf][nf][2] - mrow[mf][1]);
                float p3 = expf(sc[mf][nf][3] - mrow[mf][1]);
                psum[mf][0] += p0 + p1;
                psum[mf][1] += p2 + p3;
                *(float2*)&Ps[pr * PP + pc] = make_float2(tf32r(p0), tf32r(p1));
                *(float2*)&Ps[(pr + 8) * PP + pc] = make_float2(tf32r(p2), tf32r(p3));
            }
        }
#pragma unroll
        for (int mf = 0; mf < 2; mf++)
#pragma unroll
            for (int r2 = 0; r2 < 2; r2++) {
                float v = psum[mf][r2];
                v += __shfl_xor_sync(0xffffffffu, v, 1);
                v += __shfl_xor_sync(0xffffffffu, v, 2);
                psum[mf][r2] = v;
            }
        if (thr == 0) {
#pragma unroll
            for (int mf = 0; mf < 2; mf++)
#pragma unroll
                for (int r2 = 0; r2 < 2; r2++) {
                    int r = warp_m * 32 + mf * 16 + grp + r2 * 8;
                    redS[r * 4 + warp_n] = psum[mf][r2];
                }
        }
#pragma unroll
        for (int mf = 0; mf < 2; mf++)
#pragma unroll
            for (int nf = 0; nf < 2; nf++) {
                o[mf][nf][0] *= alpha[mf][0]; o[mf][nf][1] *= alpha[mf][0];
                o[mf][nf][2] *= alpha[mf][1]; o[mf][nf][3] *= alpha[mf][1];
            }
        cp_wait<0>();      // V_kc (and K_{kc+1}) complete
        __syncthreads();   // (b) P + sum partials + V visible

#pragma unroll
        for (int mf = 0; mf < 2; mf++)
#pragma unroll
            for (int r2 = 0; r2 < 2; r2++) {
                int r = warp_m * 32 + mf * 16 + grp + r2 * 8;
                float srow = redS[r * 4 + 0] + redS[r * 4 + 1] + redS[r * 4 + 2] + redS[r * 4 + 3];
                lsum[mf][r2] = alpha[mf][r2] * lsum[mf][r2] + srow;
            }

#pragma unroll
        for (int kb = 0; kb < 128; kb += 8) {
            uint32_t pf[2][4];
#pragma unroll
            for (int mf = 0; mf < 2; mf++)
                ldsm4(pf[mf], pLdm + (uint32_t)(mf * 16 * PP + kb) * 4);
#pragma unroll
            for (int nf = 0; nf < 2; nf++) {
                int c0 = warp_n * 16 + nf * 8;
                uint32_t b0 = __float_as_uint(Vs[(kb + thr) * PVp + c0 + grp]);
                uint32_t b1 = __float_as_uint(Vs[(kb + thr + 4) * PVp + c0 + grp]);
                mma_tf32(o[0][nf], pf[0][0], pf[0][1], pf[0][2], pf[0][3], b0, b1);
                mma_tf32(o[1][nf], pf[1][0], pf[1][1], pf[1][2], pf[1][3], b0, b1);
            }
        }
        __syncthreads();   // (c) PV reads of Ps/Vs done before next chunk overwrites
        if (kc < 2) { CPK(kc + 2, Kb[kc & 1]); cp_commit(); }
    }
#undef CPK

    float* O = OBase + (size_t)t * MTOK * H;
    float inv[2][2];
#pragma unroll
    for (int mf = 0; mf < 2; mf++)
#pragma unroll
        for (int r2 = 0; r2 < 2; r2++) inv[mf][r2] = 1.0f / lsum[mf][r2];
#pragma unroll
    for (int mf = 0; mf < 2; mf++)
#pragma unroll
        for (int nf = 0; nf < 2; nf++) {
            int q = q0 + warp_m * 32 + mf * 16 + grp;
            int col = h * DH + warp_n * 16 + nf * 8 + thr * 2;
            float* cr = o[mf][nf];
            *(float2*)(O + (size_t)(b * S + q) * H + col) =
                make_float2(tf32r(cr[0] * inv[mf][0]), tf32r(cr[1] * inv[mf][0]));
            *(float2*)(O + (size_t)(b * S + q + 8) * H + col) =
                make_float2(tf32r(cr[2] * inv[mf][1]), tf32r(cr[3] * inv[mf][1]));
        }
}

// ---------------- layernorm over 512; TFM: 0 fp32, 1 rounded, 2 dual -----------
template <bool ADD, bool GELU, int TFM>
__global__ void ln512(const float* __restrict__ X, const float* __restrict__ R,
                      const float* __restrict__ g, const float* __restrict__ bt,
                      float* __restrict__ out, float* __restrict__ out2) {
    int row = blockIdx.x, tid = threadIdx.x;
    const float* x = X + (size_t)row * H;
    float v[4];
    float s = 0.f, sq = 0.f;
#pragma unroll
    for (int i = 0; i < 4; i++) {
        int c = tid + 128 * i;
        float t = x[c];
        if (ADD) t += R[(size_t)row * H + c];
        v[i] = t; s += t; sq += t * t;
    }
#pragma unroll
    for (int o = 16; o; o >>= 1) {
        s += __shfl_xor_sync(0xffffffffu, s, o);
        sq += __shfl_xor_sync(0xffffffffu, sq, o);
    }
    __shared__ float shs[4], shq[4];
    int warp = tid >> 5, lane = tid & 31;
    if (lane == 0) { shs[warp] = s; shq[warp] = sq; }
    __syncthreads();
    s = shs[0] + shs[1] + shs[2] + shs[3];
    sq = shq[0] + shq[1] + shq[2] + shq[3];
    float mean = s * (1.0f / H);
    float var = sq * (1.0f / H) - mean * mean;
    float rstd = rsqrtf(var + EPS);
#pragma unroll
    for (int i = 0; i < 4; i++) {
        int c = tid + 128 * i;
        float y = (v[i] - mean) * rstd * g[c] + bt[c];
        if (GELU) y = geluf(y);
        if (TFM == 1) out[(size_t)row * H + c] = tf32r(y);
        else out[(size_t)row * H + c] = y;
        if (TFM == 2) out2[(size_t)row * H + c] = tf32r(y);
    }
}

// ---------------- mixer logits + softmax + weighted sum ------------------------
__global__ void mix_weighted_kernel(const float* __restrict__ W2,
                                    const float* __restrict__ b2) {
    int tok = blockIdx.x, tid = threadIdx.x;
    float p0 = 0.f, p1 = 0.f, p2 = 0.f;
    for (int i = tid; i < H; i += 128) {
        float mv = g_m[(size_t)tok * H + i];
        p0 += mv * W2[i * 3 + 0];
        p1 += mv * W2[i * 3 + 1];
        p2 += mv * W2[i * 3 + 2];
    }
    __shared__ float red0[128], red1[128], red2[128];
    red0[tid] = p0; red1[tid] = p1; red2[tid] = p2;
    __syncthreads();
    for (int s = 64; s > 0; s >>= 1) {
        if (tid < s) { red0[tid] += red0[tid + s]; red1[tid] += red1[tid + s]; red2[tid] += red2[tid + s]; }
        __syncthreads();
    }
    __shared__ float mix[3];
    if (tid == 0) {
        float l0 = red0[0] + b2[0], l1 = red1[0] + b2[1], l2 = red2[0] + b2[2];
        float mx = fmaxf(l0, fmaxf(l1, l2));
        float e0 = expf(l0 - mx), e1 = expf(l1 - mx), e2 = expf(l2 - mx);
        float inv = 1.0f / (e0 + e1 + e2);
        mix[0] = e0 * inv; mix[1] = e1 * inv; mix[2] = e2 * inv;
    }
    __syncthreads();
    float w0 = mix[0], w1 = mix[1], w2 = mix[2];
    for (int c = tid; c < H; c += 128) {
        const float* cb = g_combined + (size_t)tok * H3;
        float w = w0 * cb[c] + w1 * cb[H + c] + w2 * cb[2 * H + c];
        g_weighted[(size_t)tok * H + c] = w;
        g_weighted_tf[(size_t)tok * H + c] = tf32r(w);
    }
}

// -----------------------------------------------------------------------------
static float* symaddr(const void* sym) {
    void* p = nullptr;
    cudaGetSymbolAddress(&p, sym);
    return (float*)p;
}

extern "C" void kernel_launch(void* const* d_in, const int* in_sizes, int n_in,
                              void* d_out, int out_size) {
    const float* x          = (const float*)d_in[0];
    const float* ts         = (const float*)d_in[1];
    const float* enc_W      = (const float*)d_in[2];
    const float* enc_b      = (const float*)d_in[3];
    const float* enc_ln_g   = (const float*)d_in[4];
    const float* enc_ln_b   = (const float*)d_in[5];
    const float* qkv_W      = (const float*)d_in[6];
    const float* qkv_b      = (const float*)d_in[7];
    const float* attn_out_W = (const float*)d_in[8];
    const float* attn_out_b = (const float*)d_in[9];
    const float* mixer_W1   = (const float*)d_in[10];
    const float* mixer_b1   = (const float*)d_in[11];
    const float* mixer_ln_g = (const float*)d_in[12];
    const float* mixer_ln_b = (const float*)d_in[13];
    const float* mixer_W2   = (const float*)d_in[14];
    const float* mixer_b2   = (const float*)d_in[15];
    const float* el_qkv_W   = (const float*)d_in[16];
    const float* el_qkv_b   = (const float*)d_in[17];
    const float* el_out_W   = (const float*)d_in[18];
    const float* el_out_b   = (const float*)d_in[19];
    const float* el_ln1_g   = (const float*)d_in[20];
    const float* el_ln1_b   = (const float*)d_in[21];
    const float* el_ff_W1   = (const float*)d_in[22];
    const float* el_ff_b1   = (const float*)d_in[23];
    const float* el_ff_W2   = (const float*)d_in[24];
    const float* el_ff_b2   = (const float*)d_in[25];
    const float* el_ln2_g   = (const float*)d_in[26];
    const float* el_ln2_b   = (const float*)d_in[27];
    const float* op_W       = (const float*)d_in[28];
    const float* op_b       = (const float*)d_in[29];
    const float* op_ln_g    = (const float*)d_in[30];
    const float* op_ln_b    = (const float*)d_in[31];
    float* out = (float*)d_out;

    float* qkv3     = symaddr(g_qkv3);
    float* attn_o3  = symaddr(g_attn_o3);
    float* combined = symaddr(g_combined);
    float* combtf   = symaddr(g_combined_tf);
    float* mask3    = symaddr(g_mask3);
    float* mbuf     = symaddr(g_m);
    float* big      = symaddr(g_big);
    float* weighted = symaddr(g_weighted);
    float* wtdtf    = symaddr(g_weighted_tf);
    float* h1       = symaddr(g_h1);
    float* h1tf     = symaddr(g_h1tf);
    float* h2       = symaddr(g_h2);
    float* xtf      = symaddr(g_xtf);
    float* w_qkv = symaddr(g_w_qkv); float* w_ao = symaddr(g_w_ao);
    float* w_m1  = symaddr(g_w_m1);  float* w_eq = symaddr(g_w_eq);
    float* w_eo  = symaddr(g_w_eo);  float* w_f1 = symaddr(g_w_f1);
    float* w_f2  = symaddr(g_w_f2);  float* w_op = symaddr(g_w_op);

    constexpr int SM_G128 = 2 * (128 * 36 + 32 * 136) * 4;  // 71680
    constexpr int SM_G64  = 2 * (128 * 36 + 32 * 72) * 4;   // 55296
    cudaFuncSetAttribute(tgemm<0, 128, 1>, cudaFuncAttributeMaxDynamicSharedMemorySize, SM_G128);
    cudaFuncSetAttribute(tgemm<0, 128, 2>, cudaFuncAttributeMaxDynamicSharedMemorySize, SM_G128);
    cudaFuncSetAttribute(tgemm<1, 128, 1>, cudaFuncAttributeMaxDynamicSharedMemorySize, SM_G128);
    cudaFuncSetAttribute(tgemm<0, 64, 0>, cudaFuncAttributeMaxDynamicSharedMemorySize, SM_G64);
    cudaFuncSetAttribute(attn_fused, cudaFuncAttributeMaxDynamicSharedMemorySize, fa::SMEM_BYTES);

    // 0. one-launch tf32 pre-rounding (x + 8 weight tensors)
    {
        RtArgs a;
        a.src[0] = (const float4*)x;          a.dst[0] = (float4*)xtf;
        a.src[1] = (const float4*)qkv_W;      a.dst[1] = (float4*)w_qkv;
        a.src[2] = (const float4*)attn_out_W; a.dst[2] = (float4*)w_ao;
        a.src[3] = (const float4*)mixer_W1;   a.dst[3] = (float4*)w_m1;
        a.src[4] = (const float4*)el_qkv_W;   a.dst[4] = (float4*)w_eq;
        a.src[5] = (const float4*)el_out_W;   a.dst[5] = (float4*)w_eo;
        a.src[6] = (const float4*)el_ff_W1;   a.dst[6] = (float4*)w_f1;
        a.src[7] = (const float4*)el_ff_W2;   a.dst[7] = (float4*)w_f2;
        a.src[8] = (const float4*)op_W;       a.dst[8] = (float4*)w_op;
        roundtf_all<<<(2097152 + 255) / 256, 256>>>(a);
    }

    // 1. LUT + masks
    build_lut_kernel<<<(T * 3 * (NLUT + 1) + 127) / 128, 128>>>(enc_W, enc_b, enc_ln_g, enc_ln_b);
    mask3_kernel<<<(BSS + 255) / 256, 256>>>(ts);

    // 2. per-timescale MHA (z-batched over t), attention fully fused
    tgemm<0, 128, 1><<<dim3(H3 / 128, MTOK / 128, 3), 256, SM_G128>>>(
        xtf, H, 0L, w_qkv, H3, (long)H * H3, qkv_b, (long)H3,
        qkv3, nullptr, H3, (long)MTOK * H3, H);
    attn_fused<<<dim3(4, 96), 512, fa::SMEM_BYTES>>>(qkv3, mask3, attn_o3);
    tgemm<0, 128, 2><<<dim3(H / 128, MTOK / 128, 3), 256, SM_G128>>>(
        attn_o3, H, (long)MTOK * H, w_ao, H, (long)H * H, attn_out_b, (long)H,
        combined, combtf, H3, (long)H, H);

    // 3. mixer
    tgemm<0, 64, 0><<<dim3(H / 64, MTOK / 128, 1), 256, SM_G64>>>(
        combtf, H3, 0L, w_m1, H, 0L, mixer_b1, 0L, big, nullptr, H, 0L, H3);
    ln512<false, true, 0><<<MTOK, 128>>>(big, nullptr, mixer_ln_g, mixer_ln_b, mbuf, nullptr);
    mix_weighted_kernel<<<MTOK, 128>>>(mixer_W2, mixer_b2);

    // 4. transformer encoder layer
    tgemm<0, 128, 1><<<dim3(H3 / 128, MTOK / 128, 1), 256, SM_G128>>>(
        wtdtf, H, 0L, w_eq, H3, 0L, el_qkv_b, 0L, qkv3, nullptr, H3, 0L, H);
    attn_fused<<<dim3(4, 32), 512, fa::SMEM_BYTES>>>(qkv3, nullptr, attn_o3);
    tgemm<0, 64, 0><<<dim3(H / 64, MTOK / 128, 1), 256, SM_G64>>>(
        attn_o3, H, 0L, w_eo, H, 0L, el_out_b, 0L, mbuf, nullptr, H, 0L, H);
    ln512<true, false, 2><<<MTOK, 128>>>(weighted, mbuf, el_ln1_g, el_ln1_b, h1, h1tf);
    tgemm<1, 128, 1><<<dim3(H4 / 128, MTOK / 128, 1), 256, SM_G128>>>(
        h1tf, H, 0L, w_f1, H4, 0L, el_ff_b1, 0L, big, nullptr, H4, 0L, H);
    tgemm<0, 64, 0><<<dim3(H / 64, MTOK / 128, 1), 256, SM_G64>>>(
        big, H4, 0L, w_f2, H, 0L, el_ff_b2, 0L, mbuf, nullptr, H, 0L, H4);
    ln512<true, false, 1><<<MTOK, 128>>>(h1, mbuf, el_ln2_g, el_ln2_b, h2, nullptr);

    // 5. output projection + final LN
    tgemm<0, 64, 0><<<dim3(H / 64, MTOK / 128, 1), 256, SM_G64>>>(
        h2, H, 0L, w_op, H, 0L, op_b, 0L, mbuf, nullptr, H, 0L, H);
    ln512<false, false, 0><<<MTOK, 128>>>(mbuf, nullptr, op_ln_g, op_ln_b, out, nullptr);
}

// round 10
// speedup vs baseline: 1.0994x; 1.0870x over previous
#include <cuda_runtime.h>
#include <cstdint>

#define DI __device__ __forceinline__

namespace {
constexpr int B = 4, S = 512, H = 512, NH = 8, T = 3, DH = 64, DTS = 170;
constexpr int MTOK = B * S;
constexpr int H3 = 3 * H;
constexpr int H4 = 4 * H;
constexpr int BSS = B * S * S;
constexpr float EPS = 1e-5f;
constexpr int NLUT = 16384;
constexpr float MMAX = 5.6400f;
}

// ---------------- scratch ------------------------------------------------------
__device__ float g_qkv3[3 * MTOK * H3];
__device__ float g_attn_o3[3 * MTOK * H];
__device__ float g_combined[MTOK * H3];
__device__ float g_combined_tf[MTOK * H3];
__device__ float g_mask3[T * BSS];
__device__ float g_m[MTOK * H];
__device__ float g_big[MTOK * H4];
__device__ float g_weighted[MTOK * H];
__device__ float g_weighted_tf[MTOK * H];
__device__ float g_h1[MTOK * H];
__device__ float g_h1tf[MTOK * H];
__device__ float g_h2[MTOK * H];
__device__ float g_xtf[MTOK * H];
__device__ float g_lut[T * 3 * (NLUT + 1)];
// tf32 weight copies
__device__ float g_w_qkv[3 * H * H3];
__device__ float g_w_ao[3 * H * H];
__device__ float g_w_m1[H3 * H];
__device__ float g_w_eq[H * H3];
__device__ float g_w_eo[H * H];
__device__ float g_w_f1[H * H4];
__device__ float g_w_f2[H4 * H];
__device__ float g_w_op[H * H];

DI float geluf(float x) { return 0.5f * x * (1.0f + erff(x * 0.7071067811865475f)); }

DI uint32_t tf32cvt(float x) {
    uint32_t r;
    asm("cvt.rna.tf32.f32 %0, %1;" : "=r"(r) : "f"(x));
    return r;
}
DI float tf32r(float x) { return __uint_as_float(tf32cvt(x)); }

DI void mma_tf32(float* c, uint32_t a0, uint32_t a1, uint32_t a2, uint32_t a3,
                 uint32_t b0, uint32_t b1) {
    asm volatile(
        "mma.sync.aligned.m16n8k8.row.col.f32.tf32.tf32.f32 "
        "{%0,%1,%2,%3}, {%4,%5,%6,%7}, {%8,%9}, {%0,%1,%2,%3};"
        : "+f"(c[0]), "+f"(c[1]), "+f"(c[2]), "+f"(c[3])
        : "r"(a0), "r"(a1), "r"(a2), "r"(a3), "r"(b0), "r"(b1));
}

DI void ldsm4(uint32_t* r, uint32_t addr) {
    asm volatile("ldmatrix.sync.aligned.m8n8.x4.shared.b16 {%0,%1,%2,%3}, [%4];"
                 : "=r"(r[0]), "=r"(r[1]), "=r"(r[2]), "=r"(r[3]) : "r"(addr));
}

DI uint32_t smem_u32(const void* p) { return (uint32_t)__cvta_generic_to_shared(p); }
DI void cp16(uint32_t dst, const void* src) {
    asm volatile("cp.async.cg.shared.global [%0], [%1], 16;" :: "r"(dst), "l"(src));
}
DI void cp_commit() { asm volatile("cp.async.commit_group;"); }
template <int N> DI void cp_wait() { asm volatile("cp.async.wait_group %0;" :: "n"(N)); }

// ---------------- consolidated tf32 rounding (9 segments, one launch) ----------
struct RtArgs {
    const float4* src[9];
    float4* dst[9];
};
__global__ void roundtf_all(RtArgs a) {
    constexpr int bnd[10] = {
        0,
        262144,    // x          : 1048576 f
        851968,    // qkv_W      : +589824
        1048576,   // attn_out_W : +196608
        1245184,   // mixer_W1   : +196608
        1441792,   // el_qkv_W   : +196608
        1507328,   // el_out_W   : +65536
        1769472,   // el_ff_W1   : +262144
        2031616,   // el_ff_W2   : +262144
        2097152    // op_W       : +65536
    };
    int i = blockIdx.x * blockDim.x + threadIdx.x;
    if (i >= bnd[9]) return;
#pragma unroll
    for (int s = 0; s < 9; s++) {
        if (i >= bnd[s] && i < bnd[s + 1]) {
            int j = i - bnd[s];
            float4 v = a.src[s][j];
            float4 o;
            o.x = tf32r(v.x); o.y = tf32r(v.y); o.z = tf32r(v.z); o.w = tf32r(v.w);
            a.dst[s][j] = o;
            return;
        }
    }
}

// ---------------- LUT builder --------------------------------------------------
__global__ void build_lut_kernel(const float* __restrict__ encW,
                                 const float* __restrict__ encB,
                                 const float* __restrict__ lng,
                                 const float* __restrict__ lnb) {
    int idx = blockIdx.x * blockDim.x + threadIdx.x;
    const int total = T * 3 * (NLUT + 1);
    if (idx >= total) return;
    int j = idx % (NLUT + 1);
    int d = (idx / (NLUT + 1)) % 3;
    int t = idx / (3 * (NLUT + 1));
    float df = (float)(d - 1);
    float scale = (t == 0) ? 1.0f : ((t == 1) ? 0.1f : 0.01f);
    float m = (MMAX / NLUT) * (float)j * scale;
    const float* W0 = encW + t * 2 * DTS;
    const float* W1 = W0 + DTS;
    const float* eb = encB + t * DTS;
    const float* gg = lng + t * DTS;
    const float* bb = lnb + t * DTS;
    float s1 = 0.f, s2 = 0.f;
    for (int jj = 0; jj < DTS; jj++) {
        float e = df * W0[jj] + m * W1[jj] + eb[jj];
        s1 += e; s2 += e * e;
    }
    float mean = s1 * (1.0f / DTS);
    float var = s2 * (1.0f / DTS) - mean * mean;
    float rstd = rsqrtf(var + EPS);
    float acc = 0.f;
    for (int jj = 0; jj < DTS; jj++) {
        float e = df * W0[jj] + m * W1[jj] + eb[jj];
        acc += geluf((e - mean) * rstd * gg[jj] + bb[jj]);
    }
    g_lut[idx] = acc * (1.0f / DTS);
}

// ---------------- pairwise mask ------------------------------------------------
__global__ void mask3_kernel(const float* __restrict__ ts) {
    int idx = blockIdx.x * blockDim.x + threadIdx.x;
    if (idx >= BSS) return;
    int k = idx % S;
    int q = (idx / S) % S;
    int b = idx / (S * S);
    float dt = ts[b * S + q] - ts[b * S + k];
    int dsel = (dt > 0.f) ? 2 : ((dt < 0.f) ? 0 : 1);
    float m = log1pf(fabsf(dt) * (1.0f / 3600.0f));
    float u = m * ((float)NLUT / MMAX);
    u = fminf(u, (float)NLUT - 1e-3f);
    u = fmaxf(u, 0.0f);
    int j = (int)u;
    float f = u - (float)j;
#pragma unroll
    for (int t = 0; t < T; t++) {
        const float* lp = g_lut + (size_t)(t * 3 + dsel) * (NLUT + 1) + j;
        g_mask3[(size_t)t * BSS + idx] = lp[0] + f * (lp[1] - lp[0]);
    }
}

// ---------------- tf32 GEMM: cp.async 3-stage, BK=16 (R6 skeleton) -------------
// ldmatrix for A fragments. 8 warps as 4(M) x 2(N); warp tile 32 x (BN/2).
template <int ACT, int BN, int WMODE>
__global__ void __launch_bounds__(256) tgemm(
    const float* __restrict__ A, int lda, long sA,
    const float* __restrict__ Bm, int ldb, long sB,
    const float* __restrict__ bias, long sBias,
    float* __restrict__ C, float* __restrict__ Ctf, int ldc, long sC, int K) {
    constexpr int PA = 20, PB = BN + 8;
    constexpr int NF = BN / 16;
    extern __shared__ __align__(16) char smem_raw[];
    float* AsBase = (float*)smem_raw;
    float* BsBase = AsBase + 3 * 128 * PA;
    const int z = blockIdx.z;
    A += (size_t)z * sA; Bm += (size_t)z * sB; bias += (size_t)z * sBias;
    C += (size_t)z * sC;
    if (WMODE == 2) Ctf += (size_t)z * sC;
    const int tid = threadIdx.x;
    const int m0 = blockIdx.y * 128, n0 = blockIdx.x * BN;
    const int lane = tid & 31, wid = tid >> 5;
    const int warp_m = (wid & 3) * 32, warp_n = (wid >> 2) * (BN / 2);
    const int grp = lane >> 2, thr = lane & 3;
    const int car = tid >> 1, cac = (tid & 1) * 8;
    const float* Asrc = A + (size_t)(m0 + car) * lda + cac;
    const int cbr = tid >> 4;
    const int cbc = (BN == 128) ? ((tid & 15) * 8) : ((tid & 15) * 4);
    const float* Bsrc = Bm + (size_t)cbr * ldb + n0 + cbc;
    const uint32_t aDst = smem_u32(AsBase + car * PA + cac);
    const uint32_t bDst = smem_u32(BsBase + cbr * PB + cbc);
    constexpr uint32_t aStg = 128 * PA * 4;
    constexpr uint32_t bStg = 16 * PB * 4;

    const int kIters = K / 16;
#pragma unroll
    for (int s = 0; s < 2; s++) {
        cp16(aDst + s * aStg, Asrc + s * 16);
        cp16(aDst + s * aStg + 16, Asrc + s * 16 + 4);
        cp16(bDst + s * bStg, Bsrc + (size_t)(s * 16) * ldb);
        if (BN == 128) cp16(bDst + s * bStg + 16, Bsrc + (size_t)(s * 16) * ldb + 4);
        cp_commit();
    }
    float c[2][NF][4];
#pragma unroll
    for (int i = 0; i < 2; i++)
#pragma unroll
        for (int j = 0; j < NF; j++)
#pragma unroll
            for (int l = 0; l < 4; l++) c[i][j][l] = 0.f;

    // ldmatrix lane addressing (A fragments): conflict-free with PA=20
    const uint32_t ldmRow = (lane & 7) + ((lane >> 3) & 1) * 8;
    const uint32_t ldmCol = (lane >> 4) * 4;
    const uint32_t aLdm = smem_u32(AsBase + (warp_m + ldmRow) * PA + ldmCol);

    int sCur = 0, sNext = 2;
    for (int i = 0; i < kIters; i++) {
        cp_wait<1>();
        __syncthreads();
        int kn = (i + 2) * 16;
        if (kn < K) {
            cp16(aDst + sNext * aStg, Asrc + kn);
            cp16(aDst + sNext * aStg + 16, Asrc + kn + 4);
            cp16(bDst + sNext * bStg, Bsrc + (size_t)kn * ldb);
            if (BN == 128) cp16(bDst + sNext * bStg + 16, Bsrc + (size_t)kn * ldb + 4);
        }
        cp_commit();
        const float* Bs = BsBase + sCur * (16 * PB);
        const uint32_t aOff = aLdm + sCur * aStg;
#pragma unroll
        for (int kb = 0; kb < 16; kb += 8) {
            uint32_t af[2][4];
#pragma unroll
            for (int mf = 0; mf < 2; mf++)
                ldsm4(af[mf], aOff + (uint32_t)(mf * 16 * PA + kb) * 4);
#pragma unroll
            for (int nf = 0; nf < NF; nf++) {
                int c0 = warp_n + nf * 8;
                uint32_t b0 = __float_as_uint(Bs[(kb + thr) * PB + c0 + grp]);
                uint32_t b1 = __float_as_uint(Bs[(kb + thr + 4) * PB + c0 + grp]);
                mma_tf32(c[0][nf], af[0][0], af[0][1], af[0][2], af[0][3], b0, b1);
                mma_tf32(c[1][nf], af[1][0], af[1][1], af[1][2], af[1][3], b0, b1);
            }
        }
        sCur = (sCur == 2) ? 0 : sCur + 1;
        sNext = (sNext == 2) ? 0 : sNext + 1;
    }
#pragma unroll
    for (int mf = 0; mf < 2; mf++)
#pragma unroll
        for (int nf = 0; nf < NF; nf++) {
            int row = m0 + warp_m + mf * 16 + grp;
            int col = n0 + warp_n + nf * 8 + thr * 2;
            float bx = bias[col], by = bias[col + 1];
            float* cr = c[mf][nf];
            float v0 = cr[0] + bx, v1 = cr[1] + by;
            float v2 = cr[2] + bx, v3 = cr[3] + by;
            if (ACT == 1) { v0 = geluf(v0); v1 = geluf(v1); v2 = geluf(v2); v3 = geluf(v3); }
            float* p0 = C + (size_t)row * ldc + col;
            float* p1 = C + (size_t)(row + 8) * ldc + col;
            if (WMODE == 1) {
                *(float2*)p0 = make_float2(tf32r(v0), tf32r(v1));
                *(float2*)p1 = make_float2(tf32r(v2), tf32r(v3));
            } else {
                *(float2*)p0 = make_float2(v0, v1);
                *(float2*)p1 = make_float2(v2, v3);
                if (WMODE == 2) {
                    *(float2*)(Ctf + (size_t)row * ldc + col) = make_float2(tf32r(v0), tf32r(v1));
                    *(float2*)(Ctf + (size_t)(row + 8) * ldc + col) = make_float2(tf32r(v2), tf32r(v3));
                }
            }
        }
}

// ---------------- fused flash attention (ldmatrix Q/K/P) -----------------------
// grid (4 q-tiles, z = t*32 + b*8 + h); 512 threads = 16 warps (4M x 4N).
namespace fa {
constexpr int PQ = 68, PVp = 72, PP = 132;
constexpr int SZ_Q = 128 * PQ;
constexpr int SZ_K = 128 * PQ;
constexpr int SZ_V = 128 * PVp;
constexpr int SZ_P = 128 * PP;
constexpr int SMEM_FLOATS = SZ_Q + 2 * SZ_K + SZ_V + SZ_P + 2 * 512;
constexpr int SMEM_BYTES = SMEM_FLOATS * 4;  // 213 KB
}

__global__ void __launch_bounds__(512) attn_fused(
    const float* __restrict__ qkvBase, const float* __restrict__ maskBase,
    float* __restrict__ OBase) {
    using namespace fa;
    extern __shared__ __align__(16) float sm[];
    float* Qs = sm;
    float* Kb[2] = {Qs + SZ_Q, Qs + SZ_Q + SZ_K};
    float* Vs = Kb[1] + SZ_K;
    float* Ps = Vs + SZ_V;
    float* redM = Ps + SZ_P;
    float* redS = redM + 512;

    const int tid = threadIdx.x;
    const int z = blockIdx.y;
    const int t = z >> 5, bh = z & 31;
    const int b = bh >> 3, h = bh & 7;
    const float* qkv = qkvBase + (size_t)t * MTOK * H3;
    const int q0 = blockIdx.x * 128;
    const int lane = tid & 31, wid = tid >> 5;
    const int warp_m = wid & 3, warp_n = wid >> 2;
    const int grp = lane >> 2, thr = lane & 3;

    const int lrow = tid >> 2, lcol = (tid & 3) * 16;
    {
        const float* Qsrc = qkv + (size_t)(b * S + q0 + lrow) * H3 + h * DH + lcol;
        uint32_t d = smem_u32(Qs + lrow * PQ + lcol);
#pragma unroll
        for (int i = 0; i < 4; i++) cp16(d + 16 * i, Qsrc + 4 * i);
    }
#define CPK(KC, BUF)                                                              \
    {                                                                             \
        const float* src = qkv + (size_t)(b * S + (KC) * 128 + lrow) * H3 + H + h * DH + lcol; \
        uint32_t d = smem_u32((BUF) + lrow * PQ + lcol);                          \
        _Pragma("unroll") for (int i = 0; i < 4; i++) cp16(d + 16 * i, src + 4 * i); \
    }
    CPK(0, Kb[0]); cp_commit();
    CPK(1, Kb[1]); cp_commit();

    const float* mb = maskBase ? (maskBase + (size_t)t * BSS + (size_t)b * S * S) : nullptr;

    const uint32_t ldmRow = (lane & 7) + ((lane >> 3) & 1) * 8;
    const uint32_t ldmCol = (lane >> 4) * 4;
    const uint32_t qLdm = smem_u32(Qs + (warp_m * 32 + ldmRow) * PQ + ldmCol);
    const uint32_t pLdm = smem_u32(Ps + (warp_m * 32 + ldmRow) * PP + ldmCol);
    const uint32_t kLdmL = (uint32_t)((warp_n * 32 + ldmRow) * PQ + ldmCol) * 4;

    float o[2][2][4];
#pragma unroll
    for (int i = 0; i < 2; i++)
#pragma unroll
        for (int j = 0; j < 2; j++)
#pragma unroll
            for (int l = 0; l < 4; l++) o[i][j][l] = 0.f;
    float mrow[2][2] = {{-1e30f, -1e30f}, {-1e30f, -1e30f}};
    float lsum[2][2] = {{0.f, 0.f}, {0.f, 0.f}};

    for (int kc = 0; kc < 4; kc++) {
        {   // V chunk (single buffer; consumed after the stats phase)
            const float* src = qkv + (size_t)(b * S + kc * 128 + lrow) * H3 + 2 * H + h * DH + lcol;
            uint32_t d = smem_u32(Vs + lrow * PVp + lcol);
#pragma unroll
            for (int i = 0; i < 4; i++) cp16(d + 16 * i, src + 4 * i);
            cp_commit();
        }
        if (kc == 0) { cp_wait<2>(); __syncthreads(); }  // Q + K0 visible

        const float* Ks = Kb[kc & 1];
        const uint32_t kLdm = smem_u32(Ks) + kLdmL;
        float sc[2][4][4];
#pragma unroll
        for (int i = 0; i < 2; i++)
#pragma unroll
            for (int j = 0; j < 4; j++)
#pragma unroll
                for (int l = 0; l < 4; l++) sc[i][j][l] = 0.f;

#pragma unroll
        for (int kb = 0; kb < 64; kb += 8) {
            uint32_t qf[2][4];
#pragma unroll
            for (int mf = 0; mf < 2; mf++)
                ldsm4(qf[mf], qLdm + (uint32_t)(mf * 16 * PQ + kb) * 4);
            uint32_t kf[2][4];
#pragma unroll
            for (int p = 0; p < 2; p++)
                ldsm4(kf[p], kLdm + (uint32_t)(p * 16 * PQ + kb) * 4);
#pragma unroll
            for (int nf = 0; nf < 4; nf++) {
                uint32_t b0 = kf[nf >> 1][nf & 1];
                uint32_t b1 = kf[nf >> 1][2 + (nf & 1)];
                mma_tf32(sc[0][nf], qf[0][0], qf[0][1], qf[0][2], qf[0][3], b0, b1);
                mma_tf32(sc[1][nf], qf[1][0], qf[1][1], qf[1][2], qf[1][3], b0, b1);
            }
        }

        float pmax[2][2] = {{-1e30f, -1e30f}, {-1e30f, -1e30f}};
#pragma unroll
        for (int mf = 0; mf < 2; mf++) {
            int qr = q0 + warp_m * 32 + mf * 16 + grp;
#pragma unroll
            for (int nf = 0; nf < 4; nf++) {
                int kcol = kc * 128 + warp_n * 32 + nf * 8 + thr * 2;
                float e0 = sc[mf][nf][0] * 0.125f, e1 = sc[mf][nf][1] * 0.125f;
                float e2 = sc[mf][nf][2] * 0.125f, e3 = sc[mf][nf][3] * 0.125f;
                if (mb) {
                    float2 ma = *(const float2*)(mb + (size_t)qr * S + kcol);
                    float2 mc = *(const float2*)(mb + (size_t)(qr + 8) * S + kcol);
                    e0 += ma.x; e1 += ma.y; e2 += mc.x; e3 += mc.y;
                }
                sc[mf][nf][0] = e0; sc[mf][nf][1] = e1;
                sc[mf][nf][2] = e2; sc[mf][nf][3] = e3;
                pmax[mf][0] = fmaxf(pmax[mf][0], fmaxf(e0, e1));
                pmax[mf][1] = fmaxf(pmax[mf][1], fmaxf(e2, e3));
            }
        }
#pragma unroll
        for (int mf = 0; mf < 2; mf++)
#pragma unroll
            for (int r2 = 0; r2 < 2; r2++) {
                float v = pmax[mf][r2];
                v = fmaxf(v, __shfl_xor_sync(0xffffffffu, v, 1));
                v = fmaxf(v, __shfl_xor_sync(0xffffffffu, v, 2));
                pmax[mf][r2] = v;
            }
        if (thr == 0) {
#pragma unroll
            for (int mf = 0; mf < 2; mf++)
#pragma unroll
                for (int r2 = 0; r2 < 2; r2++) {
                    int r = warp_m * 32 + mf * 16 + grp + r2 * 8;
                    redM[r * 4 + warp_n] = pmax[mf][r2];
                }
        }
        __syncthreads();  // (a) max partials visible; all S-MMA reads of Kb done

        float alpha[2][2];
#pragma unroll
        for (int mf = 0; mf < 2; mf++)
#pragma unroll
            for (int r2 = 0; r2 < 2; r2++) {
                int r = warp_m * 32 + mf * 16 + grp + r2 * 8;
                float mc = fmaxf(fmaxf(redM[r * 4 + 0], redM[r * 4 + 1]),
                                 fmaxf(redM[r * 4 + 2], redM[r * 4 + 3]));
                float mn = fmaxf(mrow[mf][r2], mc);
                alpha[mf][r2] = expf(mrow[mf][r2] - mn);
                mrow[mf][r2] = mn;
            }

        float psum[2][2] = {{0.f, 0.f}, {0.f, 0.f}};
#pragma unroll
        for (int mf = 0; mf < 2; mf++) {
            int pr = warp_m * 32 + mf * 16 + grp;
#pragma unroll
            for (int nf = 0; nf < 4; nf++) {
                int pc = warp_n * 32 + nf * 8 + thr * 2;
                float p0 = expf(sc[mf][nf][0] - mrow[mf][0]);
                float p1 = expf(sc[mf][nf][1] - mrow[mf][0]);
                float p2 = expf(sc[mf][nf][2] - mrow[mf][1]);
                float p3 = expf(sc[mf][nf][3] - mrow[mf][1]);
                psum[mf][0] += p0 + p1;
                psum[mf][1] += p2 + p3;
                *(float2*)&Ps[pr * PP + pc] = make_float2(tf32r(p0), tf32r(p1));
                *(float2*)&Ps[(pr + 8) * PP + pc] = make_float2(tf32r(p2), tf32r(p3));
            }
        }
#pragma unroll
        for (int mf = 0; mf < 2; mf++)
#pragma unroll
            for (int r2 = 0; r2 < 2; r2++) {
                float v = psum[mf][r2];
                v += __shfl_xor_sync(0xffffffffu, v, 1);
                v += __shfl_xor_sync(0xffffffffu, v, 2);
                psum[mf][r2] = v;
            }
        if (thr == 0) {
#pragma unroll
            for (int mf = 0; mf < 2; mf++)
#pragma unroll
                for (int r2 = 0; r2 < 2; r2++) {
                    int r = warp_m * 32 + mf * 16 + grp + r2 * 8;
                    redS[r * 4 + warp_n] = psum[mf][r2];
                }
        }
#pragma unroll
        for (int mf = 0; mf < 2; mf++)
#pragma unroll
            for (int nf = 0; nf < 2; nf++) {
                o[mf][nf][0] *= alpha[mf][0]; o[mf][nf][1] *= alpha[mf][0];
                o[mf][nf][2] *= alpha[mf][1]; o[mf][nf][3] *= alpha[mf][1];
            }
        cp_wait<0>();      // V_kc (and K_{kc+1}) complete
        __syncthreads();   // (b) P + sum partials + V visible

#pragma unroll
        for (int mf = 0; mf < 2; mf++)
#pragma unroll
            for (int r2 = 0; r2 < 2; r2++) {
                int r = warp_m * 32 + mf * 16 + grp + r2 * 8;
                float srow = redS[r * 4 + 0] + redS[r * 4 + 1] + redS[r * 4 + 2] + redS[r * 4 + 3];
                lsum[mf][r2] = alpha[mf][r2] * lsum[mf][r2] + srow;
            }

#pragma unroll
        for (int kb = 0; kb < 128; kb += 8) {
            uint32_t pf[2][4];
#pragma unroll
            for (int mf = 0; mf < 2; mf++)
                ldsm4(pf[mf], pLdm + (uint32_t)(mf * 16 * PP + kb) * 4);
#pragma unroll
            for (int nf = 0; nf < 2; nf++) {
                int c0 = warp_n * 16 + nf * 8;
                uint32_t b0 = __float_as_uint(Vs[(kb + thr) * PVp + c0 + grp]);
                uint32_t b1 = __float_as_uint(Vs[(kb + thr + 4) * PVp + c0 + grp]);
                mma_tf32(o[0][nf], pf[0][0], pf[0][1], pf[0][2], pf[0][3], b0, b1);
                mma_tf32(o[1][nf], pf[1][0], pf[1][1], pf[1][2], pf[1][3], b0, b1);
            }
        }
        __syncthreads();   // (c) PV reads of Ps/Vs done before next chunk overwrites
        if (kc < 2) { CPK(kc + 2, Kb[kc & 1]); cp_commit(); }
    }
#undef CPK

    float* O = OBase + (size_t)t * MTOK * H;
    float inv[2][2];
#pragma unroll
    for (int mf = 0; mf < 2; mf++)
#pragma unroll
        for (int r2 = 0; r2 < 2; r2++) inv[mf][r2] = 1.0f / lsum[mf][r2];
#pragma unroll
    for (int mf = 0; mf < 2; mf++)
#pragma unroll
        for (int nf = 0; nf < 2; nf++) {
            int q = q0 + warp_m * 32 + mf * 16 + grp;
            int col = h * DH + warp_n * 16 + nf * 8 + thr * 2;
            float* cr = o[mf][nf];
            *(float2*)(O + (size_t)(b * S + q) * H + col) =
                make_float2(tf32r(cr[0] * inv[mf][0]), tf32r(cr[1] * inv[mf][0]));
            *(float2*)(O + (size_t)(b * S + q + 8) * H + col) =
                make_float2(tf32r(cr[2] * inv[mf][1]), tf32r(cr[3] * inv[mf][1]));
        }
}

// ---------------- layernorm over 512; TFM: 0 fp32, 1 rounded, 2 dual -----------
template <bool ADD, bool GELU, int TFM>
__global__ void ln512(const float* __restrict__ X, const float* __restrict__ R,
                      const float* __restrict__ g, const float* __restrict__ bt,
                      float* __restrict__ out, float* __restrict__ out2) {
    int row = blockIdx.x, tid = threadIdx.x;
    const float* x = X + (size_t)row * H;
    float v[4];
    float s = 0.f, sq = 0.f;
#pragma unroll
    for (int i = 0; i < 4; i++) {
        int c = tid + 128 * i;
        float t = x[c];
        if (ADD) t += R[(size_t)row * H + c];
        v[i] = t; s += t; sq += t * t;
    }
#pragma unroll
    for (int o = 16; o; o >>= 1) {
        s += __shfl_xor_sync(0xffffffffu, s, o);
        sq += __shfl_xor_sync(0xffffffffu, sq, o);
    }
    __shared__ float shs[4], shq[4];
    int warp = tid >> 5, lane = tid & 31;
    if (lane == 0) { shs[warp] = s; shq[warp] = sq; }
    __syncthreads();
    s = shs[0] + shs[1] + shs[2] + shs[3];
    sq = shq[0] + shq[1] + shq[2] + shq[3];
    float mean = s * (1.0f / H);
    float var = sq * (1.0f / H) - mean * mean;
    float rstd = rsqrtf(var + EPS);
#pragma unroll
    for (int i = 0; i < 4; i++) {
        int c = tid + 128 * i;
        float y = (v[i] - mean) * rstd * g[c] + bt[c];
        if (GELU) y = geluf(y);
        if (TFM == 1) out[(size_t)row * H + c] = tf32r(y);
        else out[(size_t)row * H + c] = y;
        if (TFM == 2) out2[(size_t)row * H + c] = tf32r(y);
    }
}

// ---------------- mixer logits + softmax + weighted sum ------------------------
__global__ void mix_weighted_kernel(const float* __restrict__ W2,
                                    const float* __restrict__ b2) {
    int tok = blockIdx.x, tid = threadIdx.x;
    float p0 = 0.f, p1 = 0.f, p2 = 0.f;
    for (int i = tid; i < H; i += 128) {
        float mv = g_m[(size_t)tok * H + i];
        p0 += mv * W2[i * 3 + 0];
        p1 += mv * W2[i * 3 + 1];
        p2 += mv * W2[i * 3 + 2];
    }
    __shared__ float red0[128], red1[128], red2[128];
    red0[tid] = p0; red1[tid] = p1; red2[tid] = p2;
    __syncthreads();
    for (int s = 64; s > 0; s >>= 1) {
        if (tid < s) { red0[tid] += red0[tid + s]; red1[tid] += red1[tid + s]; red2[tid] += red2[tid + s]; }
        __syncthreads();
    }
    __shared__ float mix[3];
    if (tid == 0) {
        float l0 = red0[0] + b2[0], l1 = red1[0] + b2[1], l2 = red2[0] + b2[2];
        float mx = fmaxf(l0, fmaxf(l1, l2));
        float e0 = expf(l0 - mx), e1 = expf(l1 - mx), e2 = expf(l2 - mx);
        float inv = 1.0f / (e0 + e1 + e2);
        mix[0] = e0 * inv; mix[1] = e1 * inv; mix[2] = e2 * inv;
    }
    __syncthreads();
    float w0 = mix[0], w1 = mix[1], w2 = mix[2];
    for (int c = tid; c < H; c += 128) {
        const float* cb = g_combined + (size_t)tok * H3;
        float w = w0 * cb[c] + w1 * cb[H + c] + w2 * cb[2 * H + c];
        g_weighted[(size_t)tok * H + c] = w;
        g_weighted_tf[(size_t)tok * H + c] = tf32r(w);
    }
}

// -----------------------------------------------------------------------------
static float* symaddr(const void* sym) {
    void* p = nullptr;
    cudaGetSymbolAddress(&p, sym);
    return (float*)p;
}

extern "C" void kernel_launch(void* const* d_in, const int* in_sizes, int n_in,
                              void* d_out, int out_size) {
    const float* x          = (const float*)d_in[0];
    const float* ts         = (const float*)d_in[1];
    const float* enc_W      = (const float*)d_in[2];
    const float* enc_b      = (const float*)d_in[3];
    const float* enc_ln_g   = (const float*)d_in[4];
    const float* enc_ln_b   = (const float*)d_in[5];
    const float* qkv_W      = (const float*)d_in[6];
    const float* qkv_b      = (const float*)d_in[7];
    const float* attn_out_W = (const float*)d_in[8];
    const float* attn_out_b = (const float*)d_in[9];
    const float* mixer_W1   = (const float*)d_in[10];
    const float* mixer_b1   = (const float*)d_in[11];
    const float* mixer_ln_g = (const float*)d_in[12];
    const float* mixer_ln_b = (const float*)d_in[13];
    const float* mixer_W2   = (const float*)d_in[14];
    const float* mixer_b2   = (const float*)d_in[15];
    const float* el_qkv_W   = (const float*)d_in[16];
    const float* el_qkv_b   = (const float*)d_in[17];
    const float* el_out_W   = (const float*)d_in[18];
    const float* el_out_b   = (const float*)d_in[19];
    const float* el_ln1_g   = (const float*)d_in[20];
    const float* el_ln1_b   = (const float*)d_in[21];
    const float* el_ff_W1   = (const float*)d_in[22];
    const float* el_ff_b1   = (const float*)d_in[23];
    const float* el_ff_W2   = (const float*)d_in[24];
    const float* el_ff_b2   = (const float*)d_in[25];
    const float* el_ln2_g   = (const float*)d_in[26];
    const float* el_ln2_b   = (const float*)d_in[27];
    const float* op_W       = (const float*)d_in[28];
    const float* op_b       = (const float*)d_in[29];
    const float* op_ln_g    = (const float*)d_in[30];
    const float* op_ln_b    = (const float*)d_in[31];
    float* out = (float*)d_out;

    float* qkv3     = symaddr(g_qkv3);
    float* attn_o3  = symaddr(g_attn_o3);
    float* combined = symaddr(g_combined);
    float* combtf   = symaddr(g_combined_tf);
    float* mask3    = symaddr(g_mask3);
    float* mbuf     = symaddr(g_m);
    float* big      = symaddr(g_big);
    float* weighted = symaddr(g_weighted);
    float* wtdtf    = symaddr(g_weighted_tf);
    float* h1       = symaddr(g_h1);
    float* h1tf     = symaddr(g_h1tf);
    float* h2       = symaddr(g_h2);
    float* xtf      = symaddr(g_xtf);
    float* w_qkv = symaddr(g_w_qkv); float* w_ao = symaddr(g_w_ao);
    float* w_m1  = symaddr(g_w_m1);  float* w_eq = symaddr(g_w_eq);
    float* w_eo  = symaddr(g_w_eo);  float* w_f1 = symaddr(g_w_f1);
    float* w_f2  = symaddr(g_w_f2);  float* w_op = symaddr(g_w_op);

    constexpr int SM_G128 = (3 * 128 * 20 + 3 * 16 * 136) * 4;  // 56832
    constexpr int SM_G64  = (3 * 128 * 20 + 3 * 16 * 72) * 4;   // 44544
    cudaFuncSetAttribute(tgemm<0, 128, 1>, cudaFuncAttributeMaxDynamicSharedMemorySize, SM_G128);
    cudaFuncSetAttribute(tgemm<0, 128, 2>, cudaFuncAttributeMaxDynamicSharedMemorySize, SM_G128);
    cudaFuncSetAttribute(tgemm<1, 128, 1>, cudaFuncAttributeMaxDynamicSharedMemorySize, SM_G128);
    cudaFuncSetAttribute(tgemm<0, 64, 0>, cudaFuncAttributeMaxDynamicSharedMemorySize, SM_G64);
    cudaFuncSetAttribute(attn_fused, cudaFuncAttributeMaxDynamicSharedMemorySize, fa::SMEM_BYTES);

    // 0. one-launch tf32 pre-rounding (x + 8 weight tensors)
    {
        RtArgs a;
        a.src[0] = (const float4*)x;          a.dst[0] = (float4*)xtf;
        a.src[1] = (const float4*)qkv_W;      a.dst[1] = (float4*)w_qkv;
        a.src[2] = (const float4*)attn_out_W; a.dst[2] = (float4*)w_ao;
        a.src[3] = (const float4*)mixer_W1;   a.dst[3] = (float4*)w_m1;
        a.src[4] = (const float4*)el_qkv_W;   a.dst[4] = (float4*)w_eq;
        a.src[5] = (const float4*)el_out_W;   a.dst[5] = (float4*)w_eo;
        a.src[6] = (const float4*)el_ff_W1;   a.dst[6] = (float4*)w_f1;
        a.src[7] = (const float4*)el_ff_W2;   a.dst[7] = (float4*)w_f2;
        a.src[8] = (const float4*)op_W;       a.dst[8] = (float4*)w_op;
        roundtf_all<<<(2097152 + 255) / 256, 256>>>(a);
    }

    // 1. LUT + masks
    build_lut_kernel<<<(T * 3 * (NLUT + 1) + 127) / 128, 128>>>(enc_W, enc_b, enc_ln_g, enc_ln_b);
    mask3_kernel<<<(BSS + 255) / 256, 256>>>(ts);

    // 2. per-timescale MHA (z-batched over t), attention fully fused
    tgemm<0, 128, 1><<<dim3(H3 / 128, MTOK / 128, 3), 256, SM_G128>>>(
        xtf, H, 0L, w_qkv, H3, (long)H * H3, qkv_b, (long)H3,
        qkv3, nullptr, H3, (long)MTOK * H3, H);
    attn_fused<<<dim3(4, 96), 512, fa::SMEM_BYTES>>>(qkv3, mask3, attn_o3);
    tgemm<0, 128, 2><<<dim3(H / 128, MTOK / 128, 3), 256, SM_G128>>>(
        attn_o3, H, (long)MTOK * H, w_ao, H, (long)H * H, attn_out_b, (long)H,
        combined, combtf, H3, (long)H, H);

    // 3. mixer
    tgemm<0, 64, 0><<<dim3(H / 64, MTOK / 128, 1), 256, SM_G64>>>(
        combtf, H3, 0L, w_m1, H, 0L, mixer_b1, 0L, big, nullptr, H, 0L, H3);
    ln512<false, true, 0><<<MTOK, 128>>>(big, nullptr, mixer_ln_g, mixer_ln_b, mbuf, nullptr);
    mix_weighted_kernel<<<MTOK, 128>>>(mixer_W2, mixer_b2);

    // 4. transformer encoder layer
    tgemm<0, 128, 1><<<dim3(H3 / 128, MTOK / 128, 1), 256, SM_G128>>>(
        wtdtf, H, 0L, w_eq, H3, 0L, el_qkv_b, 0L, qkv3, nullptr, H3, 0L, H);
    attn_fused<<<dim3(4, 32), 512, fa::SMEM_BYTES>>>(qkv3, nullptr, attn_o3);
    tgemm<0, 64, 0><<<dim3(H / 64, MTOK / 128, 1), 256, SM_G64>>>(
        attn_o3, H, 0L, w_eo, H, 0L, el_out_b, 0L, mbuf, nullptr, H, 0L, H);
    ln512<true, false, 2><<<MTOK, 128>>>(weighted, mbuf, el_ln1_g, el_ln1_b, h1, h1tf);
    tgemm<1, 128, 1><<<dim3(H4 / 128, MTOK / 128, 1), 256, SM_G128>>>(
        h1tf, H, 0L, w_f1, H4, 0L, el_ff_b1, 0L, big, nullptr, H4, 0L, H);
    tgemm<0, 64, 0><<<dim3(H / 64, MTOK / 128, 1), 256, SM_G64>>>(
        big, H4, 0L, w_f2, H, 0L, el_ff_b2, 0L, mbuf, nullptr, H, 0L, H4);
    ln512<true, false, 1><<<MTOK, 128>>>(h1, mbuf, el_ln2_g, el_ln2_b, h2, nullptr);

    // 5. output projection + final LN
    tgemm<0, 64, 0><<<dim3(H / 64, MTOK / 128, 1), 256, SM_G64>>>(
        h2, H, 0L, w_op, H, 0L, op_b, 0L, mbuf, nullptr, H, 0L, H);
    ln512<false, false, 0><<<MTOK, 128>>>(mbuf, nullptr, op_ln_g, op_ln_b, out, nullptr);
}